// round 6
// baseline (speedup 1.0000x reference)
#include <cuda_runtime.h>
#include <cuda_bf16.h>
#include <math.h>

// Problem constants (shapes fixed by the dataset)
#define MAXN 50000
#define MAXE 600000
#define HDIM 128

// ---------------- device scratch (no allocations allowed) ----------------
__device__ int   g_cnt[MAXN];          // in-degree histogram (excl self loop)
__device__ int   g_rowptr[MAXN + 1];   // CSR row pointers (by target)
__device__ int   g_cur[MAXN];          // fill cursors
__device__ int   g_esrc[MAXE];         // CSR: source node per slot
__device__ float g_ew[MAXE];           // CSR: edge weight dis[s]*dis[t]
__device__ int   g_blk[256];           // scan block sums
__device__ float g_dis[MAXN];
__device__ float g_hw [MAXN * HDIM];
__device__ float g_bufA[MAXN * HDIM];
__device__ float g_bufB[MAXN * HDIM];
__device__ float g_pool[3 * HDIM];

// vectorized global reduction (sm_90+)
__device__ __forceinline__ void red_add_v4(float* addr, float a, float b, float c, float d) {
    asm volatile("red.global.add.v4.f32 [%0], {%1, %2, %3, %4};"
                 :: "l"(addr), "f"(a), "f"(b), "f"(c), "f"(d) : "memory");
}

// ---------------- setup: cnt = 0, pool = 0 ----------------
__global__ void k_setup(int* cnt, float* pool, int n) {
    int i = blockIdx.x * blockDim.x + threadIdx.x;
    if (i < 3 * HDIM) pool[i] = 0.0f;
    if (i < n) cnt[i] = 0;
}

__global__ void k_hist(const int* __restrict__ tgt, int* __restrict__ cnt, int e) {
    int i = blockIdx.x * blockDim.x + threadIdx.x;
    if (i < e) atomicAdd(&cnt[tgt[i]], 1);
}

// dis[i] = rsqrt(deg_with_self_loop) ; deg >= 1 always
__global__ void k_dis(const int* __restrict__ cnt, float* __restrict__ dis, int n) {
    int i = blockIdx.x * blockDim.x + threadIdx.x;
    if (i < n) dis[i] = rsqrtf((float)(cnt[i] + 1));
}

// ---- 2-level exclusive scan of cnt -> rowptr ----
__global__ void k_scan1(const int* __restrict__ cnt, int* __restrict__ rp,
                        int* __restrict__ blk, int n) {
    __shared__ int sh[256];
    int t = threadIdx.x;
    int i = blockIdx.x * 256 + t;
    int v = (i < n) ? cnt[i] : 0;
    sh[t] = v;
    __syncthreads();
    for (int off = 1; off < 256; off <<= 1) {
        int x = (t >= off) ? sh[t - off] : 0;
        __syncthreads();
        sh[t] += x;
        __syncthreads();
    }
    if (i < n) rp[i] = sh[t] - v;          // exclusive within block
    if (t == 255) blk[blockIdx.x] = sh[255];
}

__global__ void k_scan2(int* __restrict__ blk, int nb) {
    __shared__ int sh[256];
    int t = threadIdx.x;
    int v = (t < nb) ? blk[t] : 0;
    sh[t] = v;
    __syncthreads();
    for (int off = 1; off < 256; off <<= 1) {
        int x = (t >= off) ? sh[t - off] : 0;
        __syncthreads();
        sh[t] += x;
        __syncthreads();
    }
    if (t < nb) blk[t] = sh[t] - v;        // exclusive
}

__global__ void k_scan3(int* __restrict__ rp, int* __restrict__ cur,
                        const int* __restrict__ blk, int n, int e) {
    int i = blockIdx.x * blockDim.x + threadIdx.x;
    if (i < n) {
        int r = rp[i] + blk[i >> 8];
        rp[i]  = r;
        cur[i] = r;
        if (i == n - 1) rp[n] = e;
    }
}

__global__ void k_fill(const int* __restrict__ src, const int* __restrict__ tgt,
                       const float* __restrict__ dis,
                       int* __restrict__ cur, int* __restrict__ esrc,
                       float* __restrict__ ew, int e) {
    int i = blockIdx.x * blockDim.x + threadIdx.x;
    if (i < e) {
        int s = src[i];
        int t = tgt[i];
        int pos = atomicAdd(&cur[t], 1);
        esrc[pos] = s;
        ew[pos]   = dis[s] * dis[t];
    }
}

// ---------------- GEMM: HW = relu?(A) @ W ----------------
// Tiles: M=128, N=128 (full), K-steps of 32. 256 threads, each computes 8x8.
#define TM 128
#define TK 32

__global__ __launch_bounds__(256) void k_gemm(
    const float* __restrict__ A, const float* __restrict__ W,
    float* __restrict__ HW, int M, int doRelu)
{
    __shared__ float As[TK][TM + 1];
    __shared__ float Ws[TK][HDIM];

    const int tid  = threadIdx.x;
    const int row0 = blockIdx.x * TM;
    const int ty   = tid >> 4;
    const int tx   = tid & 15;

    float acc[8][8];
#pragma unroll
    for (int i = 0; i < 8; i++)
#pragma unroll
        for (int j = 0; j < 8; j++) acc[i][j] = 0.0f;

    for (int k0 = 0; k0 < HDIM; k0 += TK) {
#pragma unroll
        for (int it = 0; it < 4; it++) {
            int i  = tid + it * 256;
            int r  = i >> 3;
            int kq = i & 7;
            float4 v = make_float4(0.f, 0.f, 0.f, 0.f);
            int gr = row0 + r;
            if (gr < M) v = *(const float4*)(A + (size_t)gr * HDIM + k0 + kq * 4);
            if (doRelu) {
                v.x = fmaxf(v.x, 0.f); v.y = fmaxf(v.y, 0.f);
                v.z = fmaxf(v.z, 0.f); v.w = fmaxf(v.w, 0.f);
            }
            As[kq * 4 + 0][r] = v.x;
            As[kq * 4 + 1][r] = v.y;
            As[kq * 4 + 2][r] = v.z;
            As[kq * 4 + 3][r] = v.w;
        }
#pragma unroll
        for (int it = 0; it < 4; it++) {
            int i  = tid + it * 256;
            int kk = i >> 5;
            int cq = i & 31;
            *(float4*)&Ws[kk][cq * 4] = *(const float4*)(W + (size_t)(k0 + kk) * HDIM + cq * 4);
        }
        __syncthreads();

#pragma unroll
        for (int k = 0; k < TK; k++) {
            float a[8], b[8];
#pragma unroll
            for (int i = 0; i < 8; i++) a[i] = As[k][ty * 8 + i];
#pragma unroll
            for (int j = 0; j < 8; j++) b[j] = Ws[k][tx * 8 + j];
#pragma unroll
            for (int i = 0; i < 8; i++)
#pragma unroll
                for (int j = 0; j < 8; j++) acc[i][j] += a[i] * b[j];
        }
        __syncthreads();
    }

#pragma unroll
    for (int i = 0; i < 8; i++) {
        int gr = row0 + ty * 8 + i;
        if (gr >= M) continue;
#pragma unroll
        for (int j = 0; j < 8; j += 4) {
            int c = tx * 8 + j;
            *(float4*)(HW + (size_t)gr * HDIM + c) =
                make_float4(acc[i][j], acc[i][j+1], acc[i][j+2], acc[i][j+3]);
        }
    }
}

// ---------------- CSR gather + self loop + bias + fused relu-pool ----------------
// One warp per node (grid-stride). lane handles cols lane*4..lane*4+3.
// OUT[t] = bias + dis[t]^2 * HW[t] + sum_in w * HW[src]
// pool[off + c] += relu(OUT[t][c])   (block-reduced, one RED per block)
__global__ __launch_bounds__(256) void k_gather(
    const int* __restrict__ rowptr, const int* __restrict__ esrc,
    const float* __restrict__ ew, const float* __restrict__ hw,
    const float* __restrict__ bias, const float* __restrict__ dis,
    float* __restrict__ out, float* __restrict__ poolp, int n)
{
    const int lane  = threadIdx.x & 31;
    const int wid   = (blockIdx.x * blockDim.x + threadIdx.x) >> 5;
    const int nwarp = (gridDim.x * blockDim.x) >> 5;

    float4 bb = *(const float4*)(bias + lane * 4);
    float4 pacc = make_float4(0.f, 0.f, 0.f, 0.f);

    for (int i = wid; i < n; i += nwarp) {
        float d  = dis[i];
        float d2 = d * d;
        float4 h = *(const float4*)(hw + (size_t)i * HDIM + lane * 4);
        float4 a0, a1;
        a0.x = bb.x + d2 * h.x; a0.y = bb.y + d2 * h.y;
        a0.z = bb.z + d2 * h.z; a0.w = bb.w + d2 * h.w;
        a1 = make_float4(0.f, 0.f, 0.f, 0.f);

        int e  = rowptr[i];
        int e1 = rowptr[i + 1];
        // unroll-2: two independent load chains in flight
        for (; e + 1 < e1; e += 2) {
            int   s0 = esrc[e],   s1 = esrc[e + 1];
            float w0 = ew[e],     w1 = ew[e + 1];
            float4 v0 = *(const float4*)(hw + (size_t)s0 * HDIM + lane * 4);
            float4 v1 = *(const float4*)(hw + (size_t)s1 * HDIM + lane * 4);
            a0.x += w0 * v0.x; a0.y += w0 * v0.y; a0.z += w0 * v0.z; a0.w += w0 * v0.w;
            a1.x += w1 * v1.x; a1.y += w1 * v1.y; a1.z += w1 * v1.z; a1.w += w1 * v1.w;
        }
        if (e < e1) {
            int   s0 = esrc[e];
            float w0 = ew[e];
            float4 v0 = *(const float4*)(hw + (size_t)s0 * HDIM + lane * 4);
            a0.x += w0 * v0.x; a0.y += w0 * v0.y; a0.z += w0 * v0.z; a0.w += w0 * v0.w;
        }
        a0.x += a1.x; a0.y += a1.y; a0.z += a1.z; a0.w += a1.w;
        *(float4*)(out + (size_t)i * HDIM + lane * 4) = a0;

        pacc.x += fmaxf(a0.x, 0.f);
        pacc.y += fmaxf(a0.y, 0.f);
        pacc.z += fmaxf(a0.z, 0.f);
        pacc.w += fmaxf(a0.w, 0.f);
    }

    // block-level reduce across the 8 warps, then one RED per lane of warp 0
    __shared__ float4 sh[8][32];
    int warp = threadIdx.x >> 5;
    sh[warp][lane] = pacc;
    __syncthreads();
    if (warp == 0) {
        float4 a = sh[0][lane];
#pragma unroll
        for (int w2 = 1; w2 < 8; w2++) {
            float4 b = sh[w2][lane];
            a.x += b.x; a.y += b.y; a.z += b.z; a.w += b.w;
        }
        red_add_v4(poolp + lane * 4, a.x, a.y, a.z, a.w);
    }
}

// ---------------- tiny MLP head: 384 -> 128 -> 64 -> 10 ----------------
__global__ __launch_bounds__(128) void k_mlp(
    const float* __restrict__ pool,
    const float* __restrict__ fw1, const float* __restrict__ fb1,
    const float* __restrict__ fw2, const float* __restrict__ fb2,
    const float* __restrict__ fw3, const float* __restrict__ fb3,
    float* __restrict__ out)
{
    __shared__ float p[3 * HDIM];
    __shared__ float h1[128];
    __shared__ float h2[64];
    int t = threadIdx.x;

    for (int i = t; i < 3 * HDIM; i += 128) p[i] = pool[i];
    __syncthreads();

    float s = fb1[t];
#pragma unroll 8
    for (int k = 0; k < 3 * HDIM; k++) s += p[k] * fw1[k * 128 + t];
    h1[t] = fmaxf(s, 0.0f);
    __syncthreads();

    if (t < 64) {
        float s2 = fb2[t];
#pragma unroll 8
        for (int k = 0; k < 128; k++) s2 += h1[k] * fw2[k * 64 + t];
        h2[t] = fmaxf(s2, 0.0f);
    }
    __syncthreads();

    if (t < 10) {
        float s3 = fb3[t];
#pragma unroll
        for (int k = 0; k < 64; k++) s3 += h2[k] * fw3[k * 10 + t];
        out[t] = s3;
    }
}

// ---------------- launch ----------------
extern "C" void kernel_launch(void* const* d_in, const int* in_sizes, int n_in,
                              void* d_out, int out_size)
{
    const float* x   = (const float*)d_in[0];
    const int*   ei  = (const int*)  d_in[1];
    const float* W1  = (const float*)d_in[2];
    const float* b1  = (const float*)d_in[3];
    const float* W2  = (const float*)d_in[4];
    const float* b2  = (const float*)d_in[5];
    const float* W3  = (const float*)d_in[6];
    const float* b3  = (const float*)d_in[7];
    const float* fw1 = (const float*)d_in[8];
    const float* fb1 = (const float*)d_in[9];
    const float* fw2 = (const float*)d_in[10];
    const float* fb2 = (const float*)d_in[11];
    const float* fw3 = (const float*)d_in[12];
    const float* fb3 = (const float*)d_in[13];

    const int N = in_sizes[0] / HDIM;
    const int E = in_sizes[1] / 2;
    const int* src = ei;
    const int* tgt = ei + E;

    int *cnt, *rowptr, *cur, *esrc, *blk;
    float *ew, *dis, *hw, *bufA, *bufB, *pool;
    cudaGetSymbolAddress((void**)&cnt,    g_cnt);
    cudaGetSymbolAddress((void**)&rowptr, g_rowptr);
    cudaGetSymbolAddress((void**)&cur,    g_cur);
    cudaGetSymbolAddress((void**)&esrc,   g_esrc);
    cudaGetSymbolAddress((void**)&blk,    g_blk);
    cudaGetSymbolAddress((void**)&ew,     g_ew);
    cudaGetSymbolAddress((void**)&dis,    g_dis);
    cudaGetSymbolAddress((void**)&hw,     g_hw);
    cudaGetSymbolAddress((void**)&bufA,   g_bufA);
    cudaGetSymbolAddress((void**)&bufB,   g_bufB);
    cudaGetSymbolAddress((void**)&pool,   g_pool);

    const int gemm_blocks = (N + TM - 1) / TM;
    const int NB = (N + 255) / 256;             // scan blocks (<= 256)
    const int GATHER_BLOCKS = 1024;

    // ---- CSR build (once per launch) ----
    k_setup<<<(N + 255) / 256, 256>>>(cnt, pool, N);
    k_hist <<<(E + 255) / 256, 256>>>(tgt, cnt, E);
    k_dis  <<<(N + 255) / 256, 256>>>(cnt, dis, N);
    k_scan1<<<NB, 256>>>(cnt, rowptr, blk, N);
    k_scan2<<<1, 256>>>(blk, NB);
    k_scan3<<<NB, 256>>>(rowptr, cur, blk, N, E);
    k_fill <<<(E + 255) / 256, 256>>>(src, tgt, dis, cur, esrc, ew, E);

    // ---- layer 1: x -> bufA ----
    k_gemm  <<<gemm_blocks, 256>>>(x, W1, hw, N, 0);
    k_gather<<<GATHER_BLOCKS, 256>>>(rowptr, esrc, ew, hw, b1, dis, bufA, pool, N);

    // ---- layer 2: relu(bufA) -> bufB ----
    k_gemm  <<<gemm_blocks, 256>>>(bufA, W2, hw, N, 1);
    k_gather<<<GATHER_BLOCKS, 256>>>(rowptr, esrc, ew, hw, b2, dis, bufB, pool + HDIM, N);

    // ---- layer 3: relu(bufB) -> bufA ----
    k_gemm  <<<gemm_blocks, 256>>>(bufB, W3, hw, N, 1);
    k_gather<<<GATHER_BLOCKS, 256>>>(rowptr, esrc, ew, hw, b3, dis, bufA, pool + 2 * HDIM, N);

    k_mlp<<<1, 128>>>(pool, fw1, fb1, fw2, fb2, fw3, fb3, (float*)d_out);
}

// round 7
// speedup vs baseline: 1.4861x; 1.4861x over previous
#include <cuda_runtime.h>
#include <cuda_bf16.h>
#include <math.h>

// Problem constants (shapes fixed by the dataset)
#define MAXN 50000
#define MAXE 600000
#define HDIM 128

// ---------------- device scratch (no allocations allowed) ----------------
__device__ int   g_cnt[MAXN];          // in-degree histogram (excl self loop)
__device__ int   g_rowptr[MAXN + 1];   // CSR row pointers (by target)
__device__ int   g_cur[MAXN];          // fill cursors
__device__ int2  g_epack[MAXE];        // CSR: (src, bitcast(weight)) per slot
__device__ int   g_blk[256];           // scan block sums
__device__ float g_dis[MAXN];
__device__ float g_hw [MAXN * HDIM];
__device__ float g_bufA[MAXN * HDIM];
__device__ float g_bufB[MAXN * HDIM];
__device__ float g_pool[3 * HDIM];

// vectorized global reduction (sm_90+)
__device__ __forceinline__ void red_add_v4(float* addr, float a, float b, float c, float d) {
    asm volatile("red.global.add.v4.f32 [%0], {%1, %2, %3, %4};"
                 :: "l"(addr), "f"(a), "f"(b), "f"(c), "f"(d) : "memory");
}

// ---------------- setup: cnt = 0, pool = 0 ----------------
__global__ void k_setup(int* cnt, float* pool, int n) {
    int i = blockIdx.x * blockDim.x + threadIdx.x;
    if (i < 3 * HDIM) pool[i] = 0.0f;
    if (i < n) cnt[i] = 0;
}

__global__ void k_hist(const int* __restrict__ tgt, int* __restrict__ cnt, int e) {
    int i = blockIdx.x * blockDim.x + threadIdx.x;
    if (i < e) atomicAdd(&cnt[tgt[i]], 1);
}

// dis[i] = rsqrt(deg_with_self_loop) ; deg >= 1 always
__global__ void k_dis(const int* __restrict__ cnt, float* __restrict__ dis, int n) {
    int i = blockIdx.x * blockDim.x + threadIdx.x;
    if (i < n) dis[i] = rsqrtf((float)(cnt[i] + 1));
}

// ---- 2-level exclusive scan of cnt -> rowptr ----
__global__ void k_scan1(const int* __restrict__ cnt, int* __restrict__ rp,
                        int* __restrict__ blk, int n) {
    __shared__ int sh[256];
    int t = threadIdx.x;
    int i = blockIdx.x * 256 + t;
    int v = (i < n) ? cnt[i] : 0;
    sh[t] = v;
    __syncthreads();
    for (int off = 1; off < 256; off <<= 1) {
        int x = (t >= off) ? sh[t - off] : 0;
        __syncthreads();
        sh[t] += x;
        __syncthreads();
    }
    if (i < n) rp[i] = sh[t] - v;          // exclusive within block
    if (t == 255) blk[blockIdx.x] = sh[255];
}

__global__ void k_scan2(int* __restrict__ blk, int nb) {
    __shared__ int sh[256];
    int t = threadIdx.x;
    int v = (t < nb) ? blk[t] : 0;
    sh[t] = v;
    __syncthreads();
    for (int off = 1; off < 256; off <<= 1) {
        int x = (t >= off) ? sh[t - off] : 0;
        __syncthreads();
        sh[t] += x;
        __syncthreads();
    }
    if (t < nb) blk[t] = sh[t] - v;        // exclusive
}

__global__ void k_scan3(int* __restrict__ rp, int* __restrict__ cur,
                        const int* __restrict__ blk, int n, int e) {
    int i = blockIdx.x * blockDim.x + threadIdx.x;
    if (i < n) {
        int r = rp[i] + blk[i >> 8];
        rp[i]  = r;
        cur[i] = r;
        if (i == n - 1) rp[n] = e;
    }
}

__global__ void k_fill(const int* __restrict__ src, const int* __restrict__ tgt,
                       const float* __restrict__ dis,
                       int* __restrict__ cur, int2* __restrict__ epack, int e) {
    int i = blockIdx.x * blockDim.x + threadIdx.x;
    if (i < e) {
        int s = src[i];
        int t = tgt[i];
        int pos = atomicAdd(&cur[t], 1);
        epack[pos] = make_int2(s, __float_as_int(dis[s] * dis[t]));
    }
}

// ---------------- GEMM: HW = relu?(A) @ W ----------------
// Tiles: M=128, N=128 (full), K-steps of 32. 256 threads, each computes 8x8.
#define TM 128
#define TK 32

__global__ __launch_bounds__(256) void k_gemm(
    const float* __restrict__ A, const float* __restrict__ W,
    float* __restrict__ HW, int M, int doRelu)
{
    __shared__ float As[TK][TM + 1];
    __shared__ float Ws[TK][HDIM];

    const int tid  = threadIdx.x;
    const int row0 = blockIdx.x * TM;
    const int ty   = tid >> 4;
    const int tx   = tid & 15;

    float acc[8][8];
#pragma unroll
    for (int i = 0; i < 8; i++)
#pragma unroll
        for (int j = 0; j < 8; j++) acc[i][j] = 0.0f;

    for (int k0 = 0; k0 < HDIM; k0 += TK) {
#pragma unroll
        for (int it = 0; it < 4; it++) {
            int i  = tid + it * 256;
            int r  = i >> 3;
            int kq = i & 7;
            float4 v = make_float4(0.f, 0.f, 0.f, 0.f);
            int gr = row0 + r;
            if (gr < M) v = *(const float4*)(A + (size_t)gr * HDIM + k0 + kq * 4);
            if (doRelu) {
                v.x = fmaxf(v.x, 0.f); v.y = fmaxf(v.y, 0.f);
                v.z = fmaxf(v.z, 0.f); v.w = fmaxf(v.w, 0.f);
            }
            As[kq * 4 + 0][r] = v.x;
            As[kq * 4 + 1][r] = v.y;
            As[kq * 4 + 2][r] = v.z;
            As[kq * 4 + 3][r] = v.w;
        }
#pragma unroll
        for (int it = 0; it < 4; it++) {
            int i  = tid + it * 256;
            int kk = i >> 5;
            int cq = i & 31;
            *(float4*)&Ws[kk][cq * 4] = *(const float4*)(W + (size_t)(k0 + kk) * HDIM + cq * 4);
        }
        __syncthreads();

#pragma unroll
        for (int k = 0; k < TK; k++) {
            float a[8], b[8];
#pragma unroll
            for (int i = 0; i < 8; i++) a[i] = As[k][ty * 8 + i];
#pragma unroll
            for (int j = 0; j < 8; j++) b[j] = Ws[k][tx * 8 + j];
#pragma unroll
            for (int i = 0; i < 8; i++)
#pragma unroll
                for (int j = 0; j < 8; j++) acc[i][j] += a[i] * b[j];
        }
        __syncthreads();
    }

#pragma unroll
    for (int i = 0; i < 8; i++) {
        int gr = row0 + ty * 8 + i;
        if (gr >= M) continue;
#pragma unroll
        for (int j = 0; j < 8; j += 4) {
            int c = tx * 8 + j;
            *(float4*)(HW + (size_t)gr * HDIM + c) =
                make_float4(acc[i][j], acc[i][j+1], acc[i][j+2], acc[i][j+3]);
        }
    }
}

// ---------------- CSR gather + self loop + bias + fused relu-pool ----------------
// One warp per node (grid-stride). lane handles cols lane*4..lane*4+3.
// Warp-cooperative index staging: lane L loads epack[e0+L] (coalesced), shfl
// broadcasts edge j to all lanes -> the 32 row gathers are independent (high MLP).
__global__ __launch_bounds__(256) void k_gather(
    const int* __restrict__ rowptr, const int2* __restrict__ epack,
    const float* __restrict__ hw,
    const float* __restrict__ bias, const float* __restrict__ dis,
    float* __restrict__ out, float* __restrict__ poolp, int n)
{
    const int lane  = threadIdx.x & 31;
    const int wid   = (blockIdx.x * blockDim.x + threadIdx.x) >> 5;
    const int nwarp = (gridDim.x * blockDim.x) >> 5;

    float4 bb = *(const float4*)(bias + lane * 4);
    float4 pacc = make_float4(0.f, 0.f, 0.f, 0.f);

    for (int i = wid; i < n; i += nwarp) {
        float d  = dis[i];
        float d2 = d * d;
        float4 h = *(const float4*)(hw + (size_t)i * HDIM + lane * 4);
        float4 a0;
        a0.x = bb.x + d2 * h.x; a0.y = bb.y + d2 * h.y;
        a0.z = bb.z + d2 * h.z; a0.w = bb.w + d2 * h.w;

        int e0 = rowptr[i];
        int e1 = rowptr[i + 1];
        for (int base = e0; base < e1; base += 32) {
            int m = e1 - base;                  // edges in this chunk (<= 32 used)
            if (m > 32) m = 32;
            int2 p = make_int2(0, 0);
            if (base + lane < e1) p = __ldg(&epack[base + lane]);
            // broadcast each staged edge; payload gathers are all independent
            #pragma unroll 4
            for (int j = 0; j < m; j++) {
                int   s = __shfl_sync(0xffffffffu, p.x, j);
                float w = __int_as_float(__shfl_sync(0xffffffffu, p.y, j));
                float4 v = *(const float4*)(hw + (size_t)s * HDIM + lane * 4);
                a0.x += w * v.x; a0.y += w * v.y;
                a0.z += w * v.z; a0.w += w * v.w;
            }
        }
        *(float4*)(out + (size_t)i * HDIM + lane * 4) = a0;

        pacc.x += fmaxf(a0.x, 0.f);
        pacc.y += fmaxf(a0.y, 0.f);
        pacc.z += fmaxf(a0.z, 0.f);
        pacc.w += fmaxf(a0.w, 0.f);
    }

    // block-level reduce across the 8 warps, then one RED per lane of warp 0
    __shared__ float4 sh[8][32];
    int warp = threadIdx.x >> 5;
    sh[warp][lane] = pacc;
    __syncthreads();
    if (warp == 0) {
        float4 a = sh[0][lane];
#pragma unroll
        for (int w2 = 1; w2 < 8; w2++) {
            float4 b = sh[w2][lane];
            a.x += b.x; a.y += b.y; a.z += b.z; a.w += b.w;
        }
        red_add_v4(poolp + lane * 4, a.x, a.y, a.z, a.w);
    }
}

// ---------------- tiny MLP head: 384 -> 128 -> 64 -> 10 ----------------
__global__ __launch_bounds__(128) void k_mlp(
    const float* __restrict__ pool,
    const float* __restrict__ fw1, const float* __restrict__ fb1,
    const float* __restrict__ fw2, const float* __restrict__ fb2,
    const float* __restrict__ fw3, const float* __restrict__ fb3,
    float* __restrict__ out)
{
    __shared__ float p[3 * HDIM];
    __shared__ float h1[128];
    __shared__ float h2[64];
    int t = threadIdx.x;

    for (int i = t; i < 3 * HDIM; i += 128) p[i] = pool[i];
    __syncthreads();

    float s = fb1[t];
#pragma unroll 8
    for (int k = 0; k < 3 * HDIM; k++) s += p[k] * fw1[k * 128 + t];
    h1[t] = fmaxf(s, 0.0f);
    __syncthreads();

    if (t < 64) {
        float s2 = fb2[t];
#pragma unroll 8
        for (int k = 0; k < 128; k++) s2 += h1[k] * fw2[k * 64 + t];
        h2[t] = fmaxf(s2, 0.0f);
    }
    __syncthreads();

    if (t < 10) {
        float s3 = fb3[t];
#pragma unroll
        for (int k = 0; k < 64; k++) s3 += h2[k] * fw3[k * 10 + t];
        out[t] = s3;
    }
}

// ---------------- launch ----------------
extern "C" void kernel_launch(void* const* d_in, const int* in_sizes, int n_in,
                              void* d_out, int out_size)
{
    const float* x   = (const float*)d_in[0];
    const int*   ei  = (const int*)  d_in[1];
    const float* W1  = (const float*)d_in[2];
    const float* b1  = (const float*)d_in[3];
    const float* W2  = (const float*)d_in[4];
    const float* b2  = (const float*)d_in[5];
    const float* W3  = (const float*)d_in[6];
    const float* b3  = (const float*)d_in[7];
    const float* fw1 = (const float*)d_in[8];
    const float* fb1 = (const float*)d_in[9];
    const float* fw2 = (const float*)d_in[10];
    const float* fb2 = (const float*)d_in[11];
    const float* fw3 = (const float*)d_in[12];
    const float* fb3 = (const float*)d_in[13];

    const int N = in_sizes[0] / HDIM;
    const int E = in_sizes[1] / 2;
    const int* src = ei;
    const int* tgt = ei + E;

    int *cnt, *rowptr, *cur, *blk;
    int2 *epack;
    float *dis, *hw, *bufA, *bufB, *pool;
    cudaGetSymbolAddress((void**)&cnt,    g_cnt);
    cudaGetSymbolAddress((void**)&rowptr, g_rowptr);
    cudaGetSymbolAddress((void**)&cur,    g_cur);
    cudaGetSymbolAddress((void**)&epack,  g_epack);
    cudaGetSymbolAddress((void**)&blk,    g_blk);
    cudaGetSymbolAddress((void**)&dis,    g_dis);
    cudaGetSymbolAddress((void**)&hw,     g_hw);
    cudaGetSymbolAddress((void**)&bufA,   g_bufA);
    cudaGetSymbolAddress((void**)&bufB,   g_bufB);
    cudaGetSymbolAddress((void**)&pool,   g_pool);

    const int gemm_blocks = (N + TM - 1) / TM;
    const int NB = (N + 255) / 256;             // scan blocks (<= 256)
    const int GATHER_BLOCKS = 1024;

    // ---- CSR build (once per launch) ----
    k_setup<<<(N + 255) / 256, 256>>>(cnt, pool, N);
    k_hist <<<(E + 255) / 256, 256>>>(tgt, cnt, E);
    k_dis  <<<(N + 255) / 256, 256>>>(cnt, dis, N);
    k_scan1<<<NB, 256>>>(cnt, rowptr, blk, N);
    k_scan2<<<1, 256>>>(blk, NB);
    k_scan3<<<NB, 256>>>(rowptr, cur, blk, N, E);
    k_fill <<<(E + 255) / 256, 256>>>(src, tgt, dis, cur, epack, E);

    // ---- layer 1: x -> bufA ----
    k_gemm  <<<gemm_blocks, 256>>>(x, W1, hw, N, 0);
    k_gather<<<GATHER_BLOCKS, 256>>>(rowptr, epack, hw, b1, dis, bufA, pool, N);

    // ---- layer 2: relu(bufA) -> bufB ----
    k_gemm  <<<gemm_blocks, 256>>>(bufA, W2, hw, N, 1);
    k_gather<<<GATHER_BLOCKS, 256>>>(rowptr, epack, hw, b2, dis, bufB, pool + HDIM, N);

    // ---- layer 3: relu(bufB) -> bufA ----
    k_gemm  <<<gemm_blocks, 256>>>(bufB, W3, hw, N, 1);
    k_gather<<<GATHER_BLOCKS, 256>>>(rowptr, epack, hw, b3, dis, bufA, pool + 2 * HDIM, N);

    k_mlp<<<1, 128>>>(pool, fw1, fb1, fw2, fb2, fw3, fb3, (float*)d_out);
}

// round 9
// speedup vs baseline: 1.5988x; 1.0759x over previous
#include <cuda_runtime.h>
#include <cuda_bf16.h>
#include <stdint.h>
#include <math.h>

// Problem constants (shapes fixed by the dataset)
#define MAXN 50000
#define MAXE 600000
#define HDIM 128

// ---------------- device scratch (no allocations allowed) ----------------
__device__ int   g_cnt[MAXN];          // in-degree histogram (excl self loop)
__device__ int   g_rowptr[MAXN + 1];   // CSR row pointers (by target)
__device__ int   g_cur[MAXN];          // fill cursors
__device__ int2  g_epack[MAXE];        // CSR: (src, bitcast(weight)) per slot
__device__ int   g_blk[256];           // scan block sums
__device__ float g_dis[MAXN];
__device__ float g_hw [MAXN * HDIM];
__device__ float g_bufA[MAXN * HDIM];
__device__ float g_bufB[MAXN * HDIM];
__device__ float g_pool[3 * HDIM];

// vectorized global reduction (sm_90+)
__device__ __forceinline__ void red_add_v4(float* addr, float a, float b, float c, float d) {
    asm volatile("red.global.add.v4.f32 [%0], {%1, %2, %3, %4};"
                 :: "l"(addr), "f"(a), "f"(b), "f"(c), "f"(d) : "memory");
}

// bf16 MMA: D += A(16x16) * B(16x8),  fp32 accum
__device__ __forceinline__ void mma_bf16(float* c,
    uint32_t a0, uint32_t a1, uint32_t a2, uint32_t a3,
    uint32_t b0, uint32_t b1)
{
    asm volatile(
        "mma.sync.aligned.m16n8k16.row.col.f32.bf16.bf16.f32 "
        "{%0,%1,%2,%3}, {%4,%5,%6,%7}, {%8,%9}, {%0,%1,%2,%3};"
        : "+f"(c[0]), "+f"(c[1]), "+f"(c[2]), "+f"(c[3])
        : "r"(a0), "r"(a1), "r"(a2), "r"(a3), "r"(b0), "r"(b1));
}

// ---------------- setup: cnt = 0, pool = 0 ----------------
__global__ void k_setup(int* cnt, float* pool, int n) {
    int i = blockIdx.x * blockDim.x + threadIdx.x;
    if (i < 3 * HDIM) pool[i] = 0.0f;
    if (i < n) cnt[i] = 0;
}

__global__ void k_hist(const int* __restrict__ tgt, int* __restrict__ cnt, int e) {
    int i = blockIdx.x * blockDim.x + threadIdx.x;
    if (i < e) atomicAdd(&cnt[tgt[i]], 1);
}

__global__ void k_dis(const int* __restrict__ cnt, float* __restrict__ dis, int n) {
    int i = blockIdx.x * blockDim.x + threadIdx.x;
    if (i < n) dis[i] = rsqrtf((float)(cnt[i] + 1));
}

// ---- 2-level exclusive scan of cnt -> rowptr ----
__global__ void k_scan1(const int* __restrict__ cnt, int* __restrict__ rp,
                        int* __restrict__ blk, int n) {
    __shared__ int sh[256];
    int t = threadIdx.x;
    int i = blockIdx.x * 256 + t;
    int v = (i < n) ? cnt[i] : 0;
    sh[t] = v;
    __syncthreads();
    for (int off = 1; off < 256; off <<= 1) {
        int x = (t >= off) ? sh[t - off] : 0;
        __syncthreads();
        sh[t] += x;
        __syncthreads();
    }
    if (i < n) rp[i] = sh[t] - v;
    if (t == 255) blk[blockIdx.x] = sh[255];
}

__global__ void k_scan2(int* __restrict__ blk, int nb) {
    __shared__ int sh[256];
    int t = threadIdx.x;
    int v = (t < nb) ? blk[t] : 0;
    sh[t] = v;
    __syncthreads();
    for (int off = 1; off < 256; off <<= 1) {
        int x = (t >= off) ? sh[t - off] : 0;
        __syncthreads();
        sh[t] += x;
        __syncthreads();
    }
    if (t < nb) blk[t] = sh[t] - v;
}

__global__ void k_scan3(int* __restrict__ rp, int* __restrict__ cur,
                        const int* __restrict__ blk, int n, int e) {
    int i = blockIdx.x * blockDim.x + threadIdx.x;
    if (i < n) {
        int r = rp[i] + blk[i >> 8];
        rp[i]  = r;
        cur[i] = r;
        if (i == n - 1) rp[n] = e;
    }
}

__global__ void k_fill(const int* __restrict__ src, const int* __restrict__ tgt,
                       const float* __restrict__ dis,
                       int* __restrict__ cur, int2* __restrict__ epack, int e) {
    int i = blockIdx.x * blockDim.x + threadIdx.x;
    if (i < e) {
        int s = src[i];
        int t = tgt[i];
        int pos = atomicAdd(&cur[t], 1);
        epack[pos] = make_int2(s, __float_as_int(dis[s] * dis[t]));
    }
}

// ---------------- GEMM: HW = relu?(A) @ W  via split-bf16 tensor MMA ----------------
// Block: 256 threads = 8 warps in 4(M) x 2(N); warp tile m32 x n64.
// Smem: A [row][40-pad k] hi/lo ; W transposed [n][40-pad k] hi/lo. TK=32.
#define TM 128
#define TK 32
#define KPAD 40

__global__ __launch_bounds__(256) void k_gemm(
    const float* __restrict__ A, const float* __restrict__ W,
    float* __restrict__ HW, int M, int doRelu)
{
    __shared__ __nv_bfloat16 Ah[TM][KPAD];
    __shared__ __nv_bfloat16 Al[TM][KPAD];
    __shared__ __nv_bfloat16 Bh[HDIM][KPAD];
    __shared__ __nv_bfloat16 Bl[HDIM][KPAD];

    const int tid  = threadIdx.x;
    const int lane = tid & 31;
    const int warp = tid >> 5;
    const int wm   = warp & 3;       // M group: rows wm*32..+31
    const int wn   = warp >> 2;      // N half: cols wn*64..+63
    const int g    = lane >> 2;      // 0..7
    const int tg   = lane & 3;       // 0..3
    const int row0 = blockIdx.x * TM;

    float acc[2][8][4];
#pragma unroll
    for (int mt = 0; mt < 2; mt++)
#pragma unroll
        for (int nt = 0; nt < 8; nt++)
#pragma unroll
            for (int q = 0; q < 4; q++) acc[mt][nt][q] = 0.0f;

    for (int k0 = 0; k0 < HDIM; k0 += TK) {
        // ---- load A tile (128 rows x 32 k), split into hi/lo bf16 ----
#pragma unroll
        for (int it = 0; it < 4; it++) {
            int i  = tid + it * 256;           // 0..1023 float4 slots
            int r  = i >> 3;                   // row in tile
            int kq = i & 7;                    // float4 idx: k = kq*4
            float4 v = make_float4(0.f, 0.f, 0.f, 0.f);
            int gr = row0 + r;
            if (gr < M) v = *(const float4*)(A + (size_t)gr * HDIM + k0 + kq * 4);
            if (doRelu) {
                v.x = fmaxf(v.x, 0.f); v.y = fmaxf(v.y, 0.f);
                v.z = fmaxf(v.z, 0.f); v.w = fmaxf(v.w, 0.f);
            }
            __nv_bfloat16 hx = __float2bfloat16(v.x), hy = __float2bfloat16(v.y);
            __nv_bfloat16 hz = __float2bfloat16(v.z), hw2 = __float2bfloat16(v.w);
            __nv_bfloat16 lx = __float2bfloat16(v.x - __bfloat162float(hx));
            __nv_bfloat16 ly = __float2bfloat16(v.y - __bfloat162float(hy));
            __nv_bfloat16 lz = __float2bfloat16(v.z - __bfloat162float(hz));
            __nv_bfloat16 lw = __float2bfloat16(v.w - __bfloat162float(hw2));
            int kk = kq * 4;
            *(__nv_bfloat162*)&Ah[r][kk]     = __nv_bfloat162(hx, hy);
            *(__nv_bfloat162*)&Ah[r][kk + 2] = __nv_bfloat162(hz, hw2);
            *(__nv_bfloat162*)&Al[r][kk]     = __nv_bfloat162(lx, ly);
            *(__nv_bfloat162*)&Al[r][kk + 2] = __nv_bfloat162(lz, lw);
        }
        // ---- load W tile (32 k x 128 n) transposed into [n][k], split hi/lo ----
#pragma unroll
        for (int it = 0; it < 16; it++) {
            int i  = tid + it * 256;           // 0..4095
            int kk = i >> 7;                   // 0..31
            int nn = i & 127;
            float f = W[(size_t)(k0 + kk) * HDIM + nn];
            __nv_bfloat16 h = __float2bfloat16(f);
            __nv_bfloat16 l = __float2bfloat16(f - __bfloat162float(h));
            Bh[nn][kk] = h;
            Bl[nn][kk] = l;
        }
        __syncthreads();

        // ---- 2 x k16 MMA steps ----
#pragma unroll
        for (int ks = 0; ks < 2; ks++) {
            const int kb = ks * 16;
            uint32_t Ahf[2][4], Alf[2][4];
#pragma unroll
            for (int mt = 0; mt < 2; mt++) {
                int r = wm * 32 + mt * 16 + g;
                Ahf[mt][0] = *(const uint32_t*)&Ah[r    ][kb + tg * 2];
                Ahf[mt][1] = *(const uint32_t*)&Ah[r + 8][kb + tg * 2];
                Ahf[mt][2] = *(const uint32_t*)&Ah[r    ][kb + tg * 2 + 8];
                Ahf[mt][3] = *(const uint32_t*)&Ah[r + 8][kb + tg * 2 + 8];
                Alf[mt][0] = *(const uint32_t*)&Al[r    ][kb + tg * 2];
                Alf[mt][1] = *(const uint32_t*)&Al[r + 8][kb + tg * 2];
                Alf[mt][2] = *(const uint32_t*)&Al[r    ][kb + tg * 2 + 8];
                Alf[mt][3] = *(const uint32_t*)&Al[r + 8][kb + tg * 2 + 8];
            }
#pragma unroll
            for (int nt = 0; nt < 8; nt++) {
                int c = wn * 64 + nt * 8 + g;
                uint32_t bh0 = *(const uint32_t*)&Bh[c][kb + tg * 2];
                uint32_t bh1 = *(const uint32_t*)&Bh[c][kb + tg * 2 + 8];
                uint32_t bl0 = *(const uint32_t*)&Bl[c][kb + tg * 2];
                uint32_t bl1 = *(const uint32_t*)&Bl[c][kb + tg * 2 + 8];
#pragma unroll
                for (int mt = 0; mt < 2; mt++) {
                    mma_bf16(acc[mt][nt], Ahf[mt][0], Ahf[mt][1], Ahf[mt][2], Ahf[mt][3], bh0, bh1);
                    mma_bf16(acc[mt][nt], Ahf[mt][0], Ahf[mt][1], Ahf[mt][2], Ahf[mt][3], bl0, bl1);
                    mma_bf16(acc[mt][nt], Alf[mt][0], Alf[mt][1], Alf[mt][2], Alf[mt][3], bh0, bh1);
                }
            }
        }
        __syncthreads();
    }

    // ---- epilogue: float2 stores ----
#pragma unroll
    for (int mt = 0; mt < 2; mt++) {
        int r = row0 + wm * 32 + mt * 16 + g;
#pragma unroll
        for (int nt = 0; nt < 8; nt++) {
            int c = wn * 64 + nt * 8 + tg * 2;
            if (r < M)
                *(float2*)(HW + (size_t)r * HDIM + c) =
                    make_float2(acc[mt][nt][0], acc[mt][nt][1]);
            if (r + 8 < M)
                *(float2*)(HW + (size_t)(r + 8) * HDIM + c) =
                    make_float2(acc[mt][nt][2], acc[mt][nt][3]);
        }
    }
}

// ---------------- CSR gather + self loop + bias + fused relu-pool ----------------
__global__ __launch_bounds__(256) void k_gather(
    const int* __restrict__ rowptr, const int2* __restrict__ epack,
    const float* __restrict__ hw,
    const float* __restrict__ bias, const float* __restrict__ dis,
    float* __restrict__ out, float* __restrict__ poolp, int n)
{
    const int lane  = threadIdx.x & 31;
    const int wid   = (blockIdx.x * blockDim.x + threadIdx.x) >> 5;
    const int nwarp = (gridDim.x * blockDim.x) >> 5;

    float4 bb = *(const float4*)(bias + lane * 4);
    float4 pacc = make_float4(0.f, 0.f, 0.f, 0.f);

    for (int i = wid; i < n; i += nwarp) {
        float d  = dis[i];
        float d2 = d * d;
        float4 h = *(const float4*)(hw + (size_t)i * HDIM + lane * 4);
        float4 a0;
        a0.x = bb.x + d2 * h.x; a0.y = bb.y + d2 * h.y;
        a0.z = bb.z + d2 * h.z; a0.w = bb.w + d2 * h.w;

        int e0 = rowptr[i];
        int e1 = rowptr[i + 1];
        for (int base = e0; base < e1; base += 32) {
            int m = e1 - base;
            if (m > 32) m = 32;
            int2 p = make_int2(0, 0);
            if (base + lane < e1) p = __ldg(&epack[base + lane]);
            #pragma unroll 4
            for (int j = 0; j < m; j++) {
                int   s = __shfl_sync(0xffffffffu, p.x, j);
                float w = __int_as_float(__shfl_sync(0xffffffffu, p.y, j));
                float4 v = *(const float4*)(hw + (size_t)s * HDIM + lane * 4);
                a0.x += w * v.x; a0.y += w * v.y;
                a0.z += w * v.z; a0.w += w * v.w;
            }
        }
        *(float4*)(out + (size_t)i * HDIM + lane * 4) = a0;

        pacc.x += fmaxf(a0.x, 0.f);
        pacc.y += fmaxf(a0.y, 0.f);
        pacc.z += fmaxf(a0.z, 0.f);
        pacc.w += fmaxf(a0.w, 0.f);
    }

    __shared__ float4 sh[8][32];
    int warp = threadIdx.x >> 5;
    sh[warp][lane] = pacc;
    __syncthreads();
    if (warp == 0) {
        float4 a = sh[0][lane];
#pragma unroll
        for (int w2 = 1; w2 < 8; w2++) {
            float4 b = sh[w2][lane];
            a.x += b.x; a.y += b.y; a.z += b.z; a.w += b.w;
        }
        red_add_v4(poolp + lane * 4, a.x, a.y, a.z, a.w);
    }
}

// ---------------- tiny MLP head: 384 -> 128 -> 64 -> 10 ----------------
__global__ __launch_bounds__(128) void k_mlp(
    const float* __restrict__ pool,
    const float* __restrict__ fw1, const float* __restrict__ fb1,
    const float* __restrict__ fw2, const float* __restrict__ fb2,
    const float* __restrict__ fw3, const float* __restrict__ fb3,
    float* __restrict__ out)
{
    __shared__ float p[3 * HDIM];
    __shared__ float h1[128];
    __shared__ float h2[64];
    int t = threadIdx.x;

    for (int i = t; i < 3 * HDIM; i += 128) p[i] = pool[i];
    __syncthreads();

    float s = fb1[t];
#pragma unroll 8
    for (int k = 0; k < 3 * HDIM; k++) s += p[k] * fw1[k * 128 + t];
    h1[t] = fmaxf(s, 0.0f);
    __syncthreads();

    if (t < 64) {
        float s2 = fb2[t];
#pragma unroll 8
        for (int k = 0; k < 128; k++) s2 += h1[k] * fw2[k * 64 + t];
        h2[t] = fmaxf(s2, 0.0f);
    }
    __syncthreads();

    if (t < 10) {
        float s3 = fb3[t];
#pragma unroll
        for (int k = 0; k < 64; k++) s3 += h2[k] * fw3[k * 10 + t];
        out[t] = s3;
    }
}

// ---------------- launch ----------------
extern "C" void kernel_launch(void* const* d_in, const int* in_sizes, int n_in,
                              void* d_out, int out_size)
{
    const float* x   = (const float*)d_in[0];
    const int*   ei  = (const int*)  d_in[1];
    const float* W1  = (const float*)d_in[2];
    const float* b1  = (const float*)d_in[3];
    const float* W2  = (const float*)d_in[4];
    const float* b2  = (const float*)d_in[5];
    const float* W3  = (const float*)d_in[6];
    const float* b3  = (const float*)d_in[7];
    const float* fw1 = (const float*)d_in[8];
    const float* fb1 = (const float*)d_in[9];
    const float* fw2 = (const float*)d_in[10];
    const float* fb2 = (const float*)d_in[11];
    const float* fw3 = (const float*)d_in[12];
    const float* fb3 = (const float*)d_in[13];

    const int N = in_sizes[0] / HDIM;
    const int E = in_sizes[1] / 2;
    const int* src = ei;
    const int* tgt = ei + E;

    int *cnt, *rowptr, *cur, *blk;
    int2 *epack;
    float *dis, *hw, *bufA, *bufB, *pool;
    cudaGetSymbolAddress((void**)&cnt,    g_cnt);
    cudaGetSymbolAddress((void**)&rowptr, g_rowptr);
    cudaGetSymbolAddress((void**)&cur,    g_cur);
    cudaGetSymbolAddress((void**)&epack,  g_epack);
    cudaGetSymbolAddress((void**)&blk,    g_blk);
    cudaGetSymbolAddress((void**)&dis,    g_dis);
    cudaGetSymbolAddress((void**)&hw,     g_hw);
    cudaGetSymbolAddress((void**)&bufA,   g_bufA);
    cudaGetSymbolAddress((void**)&bufB,   g_bufB);
    cudaGetSymbolAddress((void**)&pool,   g_pool);

    const int gemm_blocks = (N + TM - 1) / TM;
    const int NB = (N + 255) / 256;
    const int GATHER_BLOCKS = 1024;

    // ---- CSR build (once per launch) ----
    k_setup<<<(N + 255) / 256, 256>>>(cnt, pool, N);
    k_hist <<<(E + 255) / 256, 256>>>(tgt, cnt, E);
    k_dis  <<<(N + 255) / 256, 256>>>(cnt, dis, N);
    k_scan1<<<NB, 256>>>(cnt, rowptr, blk, N);
    k_scan2<<<1, 256>>>(blk, NB);
    k_scan3<<<NB, 256>>>(rowptr, cur, blk, N, E);
    k_fill <<<(E + 255) / 256, 256>>>(src, tgt, dis, cur, epack, E);

    // ---- layer 1: x -> bufA ----
    k_gemm  <<<gemm_blocks, 256>>>(x, W1, hw, N, 0);
    k_gather<<<GATHER_BLOCKS, 256>>>(rowptr, epack, hw, b1, dis, bufA, pool, N);

    // ---- layer 2: relu(bufA) -> bufB ----
    k_gemm  <<<gemm_blocks, 256>>>(bufA, W2, hw, N, 1);
    k_gather<<<GATHER_BLOCKS, 256>>>(rowptr, epack, hw, b2, dis, bufB, pool + HDIM, N);

    // ---- layer 3: relu(bufB) -> bufA ----
    k_gemm  <<<gemm_blocks, 256>>>(bufB, W3, hw, N, 1);
    k_gather<<<GATHER_BLOCKS, 256>>>(rowptr, epack, hw, b3, dis, bufA, pool + 2 * HDIM, N);

    k_mlp<<<1, 128>>>(pool, fw1, fb1, fw2, fb2, fw3, fb3, (float*)d_out);
}

// round 11
// speedup vs baseline: 1.7997x; 1.1256x over previous
#include <cuda_runtime.h>
#include <cuda_bf16.h>
#include <stdint.h>
#include <math.h>

// Problem constants (shapes fixed by the dataset)
#define MAXN 50000
#define MAXE 600000
#define HDIM 128

// ---------------- device scratch (no allocations allowed) ----------------
__device__ int   g_cnt[MAXN];
__device__ int   g_rowptr[MAXN + 1];
__device__ int   g_cur[MAXN];
__device__ int2  g_epack[MAXE];
__device__ int   g_blk[256];
__device__ float g_dis[MAXN];
__device__ float g_hw [MAXN * HDIM];               // GEMM output (fp32)
__device__ __nv_bfloat16 g_xh[MAXN * HDIM];        // current layer input, hi plane
__device__ __nv_bfloat16 g_xl[MAXN * HDIM];        // current layer input, lo plane
__device__ __nv_bfloat16 g_wh[HDIM * HDIM];        // W^T hi plane [n][k]
__device__ __nv_bfloat16 g_wl[HDIM * HDIM];        // W^T lo plane [n][k]
__device__ float g_pool[3 * HDIM];

__device__ __forceinline__ void red_add_v4(float* addr, float a, float b, float c, float d) {
    asm volatile("red.global.add.v4.f32 [%0], {%1, %2, %3, %4};"
                 :: "l"(addr), "f"(a), "f"(b), "f"(c), "f"(d) : "memory");
}

__device__ __forceinline__ void mma_bf16(float* c,
    uint32_t a0, uint32_t a1, uint32_t a2, uint32_t a3,
    uint32_t b0, uint32_t b1)
{
    asm volatile(
        "mma.sync.aligned.m16n8k16.row.col.f32.bf16.bf16.f32 "
        "{%0,%1,%2,%3}, {%4,%5,%6,%7}, {%8,%9}, {%0,%1,%2,%3};"
        : "+f"(c[0]), "+f"(c[1]), "+f"(c[2]), "+f"(c[3])
        : "r"(a0), "r"(a1), "r"(a2), "r"(a3), "r"(b0), "r"(b1));
}

__device__ __forceinline__ uint32_t pack_bf16x2(__nv_bfloat16 a, __nv_bfloat16 b) {
    return (uint32_t)__bfloat16_as_ushort(a) | ((uint32_t)__bfloat16_as_ushort(b) << 16);
}

// ---------------- setup ----------------
__global__ void k_setup(int* cnt, float* pool, int n) {
    int i = blockIdx.x * blockDim.x + threadIdx.x;
    if (i < 3 * HDIM) pool[i] = 0.0f;
    if (i < n) cnt[i] = 0;
}

__global__ void k_hist(const int* __restrict__ tgt, int* __restrict__ cnt, int e) {
    int i = blockIdx.x * blockDim.x + threadIdx.x;
    if (i < e) atomicAdd(&cnt[tgt[i]], 1);
}

__global__ void k_dis(const int* __restrict__ cnt, float* __restrict__ dis, int n) {
    int i = blockIdx.x * blockDim.x + threadIdx.x;
    if (i < n) dis[i] = rsqrtf((float)(cnt[i] + 1));
}

// ---- 2-level exclusive scan of cnt -> rowptr ----
__global__ void k_scan1(const int* __restrict__ cnt, int* __restrict__ rp,
                        int* __restrict__ blk, int n) {
    __shared__ int sh[256];
    int t = threadIdx.x;
    int i = blockIdx.x * 256 + t;
    int v = (i < n) ? cnt[i] : 0;
    sh[t] = v;
    __syncthreads();
    for (int off = 1; off < 256; off <<= 1) {
        int x = (t >= off) ? sh[t - off] : 0;
        __syncthreads();
        sh[t] += x;
        __syncthreads();
    }
    if (i < n) rp[i] = sh[t] - v;
    if (t == 255) blk[blockIdx.x] = sh[255];
}

__global__ void k_scan2(int* __restrict__ blk, int nb) {
    __shared__ int sh[256];
    int t = threadIdx.x;
    int v = (t < nb) ? blk[t] : 0;
    sh[t] = v;
    __syncthreads();
    for (int off = 1; off < 256; off <<= 1) {
        int x = (t >= off) ? sh[t - off] : 0;
        __syncthreads();
        sh[t] += x;
        __syncthreads();
    }
    if (t < nb) blk[t] = sh[t] - v;
}

__global__ void k_scan3(int* __restrict__ rp, int* __restrict__ cur,
                        const int* __restrict__ blk, int n, int e) {
    int i = blockIdx.x * blockDim.x + threadIdx.x;
    if (i < n) {
        int r = rp[i] + blk[i >> 8];
        rp[i]  = r;
        cur[i] = r;
        if (i == n - 1) rp[n] = e;
    }
}

__global__ void k_fill(const int* __restrict__ src, const int* __restrict__ tgt,
                       const float* __restrict__ dis,
                       int* __restrict__ cur, int2* __restrict__ epack, int e) {
    int i = blockIdx.x * blockDim.x + threadIdx.x;
    if (i < e) {
        int s = src[i];
        int t = tgt[i];
        int pos = atomicAdd(&cur[t], 1);
        epack[pos] = make_int2(s, __float_as_int(dis[s] * dis[t]));
    }
}

// ---------------- split-bf16 conversions (hoisted out of GEMM) ----------------
// x -> planes, no relu. One float4 per thread.
__global__ void k_convX(const float* __restrict__ x,
                        __nv_bfloat16* __restrict__ xh, __nv_bfloat16* __restrict__ xl,
                        int total4) {
    int i = blockIdx.x * blockDim.x + threadIdx.x;
    if (i >= total4) return;
    float4 v = *(const float4*)(x + (size_t)i * 4);
    __nv_bfloat16 hx = __float2bfloat16(v.x), hy = __float2bfloat16(v.y);
    __nv_bfloat16 hz = __float2bfloat16(v.z), hw = __float2bfloat16(v.w);
    uint2 ph, pl;
    ph.x = pack_bf16x2(hx, hy);
    ph.y = pack_bf16x2(hz, hw);
    pl.x = pack_bf16x2(__float2bfloat16(v.x - __bfloat162float(hx)),
                       __float2bfloat16(v.y - __bfloat162float(hy)));
    pl.y = pack_bf16x2(__float2bfloat16(v.z - __bfloat162float(hz)),
                       __float2bfloat16(v.w - __bfloat162float(hw)));
    *(uint2*)(xh + (size_t)i * 4) = ph;
    *(uint2*)(xl + (size_t)i * 4) = pl;
}

// W [k][n] fp32 -> transposed planes [n][k] bf16 hi/lo. 128x128, tiny.
__global__ void k_convW(const float* __restrict__ W,
                        __nv_bfloat16* __restrict__ wh, __nv_bfloat16* __restrict__ wl) {
    int idx = blockIdx.x * blockDim.x + threadIdx.x;   // 0..16383
    int k = idx >> 7, n = idx & 127;
    float f = W[idx];
    __nv_bfloat16 h = __float2bfloat16(f);
    wh[n * HDIM + k] = h;
    wl[n * HDIM + k] = __float2bfloat16(f - __bfloat162float(h));
}

// ---------------- GEMM: HW = planes(A) @ planes(W)  (3-term split-bf16 MMA) --------
// Block: 256 threads = 8 warps in 4(M) x 2(N); warp tile m32 x n64. TK=32.
#define TM 128
#define TK 32
#define KPAD 40

__global__ __launch_bounds__(256) void k_gemm(
    const __nv_bfloat16* __restrict__ Ahp, const __nv_bfloat16* __restrict__ Alp,
    const __nv_bfloat16* __restrict__ Bhp, const __nv_bfloat16* __restrict__ Blp,
    float* __restrict__ HW, int M)
{
    __shared__ __nv_bfloat16 Ah[TM][KPAD];
    __shared__ __nv_bfloat16 Al[TM][KPAD];
    __shared__ __nv_bfloat16 Bh[HDIM][KPAD];
    __shared__ __nv_bfloat16 Bl[HDIM][KPAD];

    const int tid  = threadIdx.x;
    const int lane = tid & 31;
    const int warp = tid >> 5;
    const int wm   = warp & 3;
    const int wn   = warp >> 2;
    const int g    = lane >> 2;
    const int tg   = lane & 3;
    const int row0 = blockIdx.x * TM;

    float acc[2][8][4];
#pragma unroll
    for (int mt = 0; mt < 2; mt++)
#pragma unroll
        for (int nt = 0; nt < 8; nt++)
#pragma unroll
            for (int q = 0; q < 4; q++) acc[mt][nt][q] = 0.0f;

    for (int k0 = 0; k0 < HDIM; k0 += TK) {
        // ---- load tiles: 512 uint4 per plane (128 rows x 32 bf16), 2 per thread ----
#pragma unroll
        for (int it = 0; it < 2; it++) {
            int i = tid + it * 256;        // 0..511
            int r = i >> 2;                // row / n-col
            int q = i & 3;                 // which 8-element group: k = q*8
            int kk = q * 8;
            // A planes (bounds-guarded rows)
            uint4 vh = make_uint4(0, 0, 0, 0), vl = make_uint4(0, 0, 0, 0);
            if (row0 + r < M) {
                vh = *(const uint4*)(Ahp + (size_t)(row0 + r) * HDIM + k0 + kk);
                vl = *(const uint4*)(Alp + (size_t)(row0 + r) * HDIM + k0 + kk);
            }
            *(uint2*)&Ah[r][kk]     = make_uint2(vh.x, vh.y);
            *(uint2*)&Ah[r][kk + 4] = make_uint2(vh.z, vh.w);
            *(uint2*)&Al[r][kk]     = make_uint2(vl.x, vl.y);
            *(uint2*)&Al[r][kk + 4] = make_uint2(vl.z, vl.w);
            // B planes (always full 128 rows)
            uint4 bh = *(const uint4*)(Bhp + (size_t)r * HDIM + k0 + kk);
            uint4 bl = *(const uint4*)(Blp + (size_t)r * HDIM + k0 + kk);
            *(uint2*)&Bh[r][kk]     = make_uint2(bh.x, bh.y);
            *(uint2*)&Bh[r][kk + 4] = make_uint2(bh.z, bh.w);
            *(uint2*)&Bl[r][kk]     = make_uint2(bl.x, bl.y);
            *(uint2*)&Bl[r][kk + 4] = make_uint2(bl.z, bl.w);
        }
        __syncthreads();

#pragma unroll
        for (int ks = 0; ks < 2; ks++) {
            const int kb = ks * 16;
            uint32_t Ahf[2][4], Alf[2][4];
#pragma unroll
            for (int mt = 0; mt < 2; mt++) {
                int r = wm * 32 + mt * 16 + g;
                Ahf[mt][0] = *(const uint32_t*)&Ah[r    ][kb + tg * 2];
                Ahf[mt][1] = *(const uint32_t*)&Ah[r + 8][kb + tg * 2];
                Ahf[mt][2] = *(const uint32_t*)&Ah[r    ][kb + tg * 2 + 8];
                Ahf[mt][3] = *(const uint32_t*)&Ah[r + 8][kb + tg * 2 + 8];
                Alf[mt][0] = *(const uint32_t*)&Al[r    ][kb + tg * 2];
                Alf[mt][1] = *(const uint32_t*)&Al[r + 8][kb + tg * 2];
                Alf[mt][2] = *(const uint32_t*)&Al[r    ][kb + tg * 2 + 8];
                Alf[mt][3] = *(const uint32_t*)&Al[r + 8][kb + tg * 2 + 8];
            }
#pragma unroll
            for (int nt = 0; nt < 8; nt++) {
                int c = wn * 64 + nt * 8 + g;
                uint32_t bh0 = *(const uint32_t*)&Bh[c][kb + tg * 2];
                uint32_t bh1 = *(const uint32_t*)&Bh[c][kb + tg * 2 + 8];
                uint32_t bl0 = *(const uint32_t*)&Bl[c][kb + tg * 2];
                uint32_t bl1 = *(const uint32_t*)&Bl[c][kb + tg * 2 + 8];
#pragma unroll
                for (int mt = 0; mt < 2; mt++) {
                    mma_bf16(acc[mt][nt], Ahf[mt][0], Ahf[mt][1], Ahf[mt][2], Ahf[mt][3], bh0, bh1);
                    mma_bf16(acc[mt][nt], Ahf[mt][0], Ahf[mt][1], Ahf[mt][2], Ahf[mt][3], bl0, bl1);
                    mma_bf16(acc[mt][nt], Alf[mt][0], Alf[mt][1], Alf[mt][2], Alf[mt][3], bh0, bh1);
                }
            }
        }
        __syncthreads();
    }

#pragma unroll
    for (int mt = 0; mt < 2; mt++) {
        int r = row0 + wm * 32 + mt * 16 + g;
#pragma unroll
        for (int nt = 0; nt < 8; nt++) {
            int c = wn * 64 + nt * 8 + tg * 2;
            if (r < M)
                *(float2*)(HW + (size_t)r * HDIM + c) =
                    make_float2(acc[mt][nt][0], acc[mt][nt][1]);
            if (r + 8 < M)
                *(float2*)(HW + (size_t)(r + 8) * HDIM + c) =
                    make_float2(acc[mt][nt][2], acc[mt][nt][3]);
        }
    }
}

// ---------------- CSR gather + self loop + bias + relu-pool + bf16 plane output ----
__global__ __launch_bounds__(256) void k_gather(
    const int* __restrict__ rowptr, const int2* __restrict__ epack,
    const float* __restrict__ hw,
    const float* __restrict__ bias, const float* __restrict__ dis,
    __nv_bfloat16* __restrict__ outh, __nv_bfloat16* __restrict__ outl,
    int writePlanes, float* __restrict__ poolp, int n)
{
    const int lane  = threadIdx.x & 31;
    const int wid   = (blockIdx.x * blockDim.x + threadIdx.x) >> 5;
    const int nwarp = (gridDim.x * blockDim.x) >> 5;

    float4 bb = *(const float4*)(bias + lane * 4);
    float4 pacc = make_float4(0.f, 0.f, 0.f, 0.f);

    for (int i = wid; i < n; i += nwarp) {
        float d  = dis[i];
        float d2 = d * d;
        float4 h = *(const float4*)(hw + (size_t)i * HDIM + lane * 4);
        float4 a0;
        a0.x = bb.x + d2 * h.x; a0.y = bb.y + d2 * h.y;
        a0.z = bb.z + d2 * h.z; a0.w = bb.w + d2 * h.w;

        int e0 = rowptr[i];
        int e1 = rowptr[i + 1];
        for (int base = e0; base < e1; base += 32) {
            int m = e1 - base;
            if (m > 32) m = 32;
            int2 p = make_int2(0, 0);
            if (base + lane < e1) p = __ldg(&epack[base + lane]);
            #pragma unroll 4
            for (int j = 0; j < m; j++) {
                int   s = __shfl_sync(0xffffffffu, p.x, j);
                float w = __int_as_float(__shfl_sync(0xffffffffu, p.y, j));
                float4 v = *(const float4*)(hw + (size_t)s * HDIM + lane * 4);
                a0.x += w * v.x; a0.y += w * v.y;
                a0.z += w * v.z; a0.w += w * v.w;
            }
        }

        float rx = fmaxf(a0.x, 0.f), ry = fmaxf(a0.y, 0.f);
        float rz = fmaxf(a0.z, 0.f), rw = fmaxf(a0.w, 0.f);
        pacc.x += rx; pacc.y += ry; pacc.z += rz; pacc.w += rw;

        if (writePlanes) {
            __nv_bfloat16 hx = __float2bfloat16(rx), hy = __float2bfloat16(ry);
            __nv_bfloat16 hz = __float2bfloat16(rz), hw2 = __float2bfloat16(rw);
            uint2 ph, pl;
            ph.x = pack_bf16x2(hx, hy);
            ph.y = pack_bf16x2(hz, hw2);
            pl.x = pack_bf16x2(__float2bfloat16(rx - __bfloat162float(hx)),
                               __float2bfloat16(ry - __bfloat162float(hy)));
            pl.y = pack_bf16x2(__float2bfloat16(rz - __bfloat162float(hz)),
                               __float2bfloat16(rw - __bfloat162float(hw2)));
            *(uint2*)(outh + (size_t)i * HDIM + lane * 4) = ph;
            *(uint2*)(outl + (size_t)i * HDIM + lane * 4) = pl;
        }
    }

    __shared__ float4 sh[8][32];
    int warp = threadIdx.x >> 5;
    sh[warp][lane] = pacc;
    __syncthreads();
    if (warp == 0) {
        float4 a = sh[0][lane];
#pragma unroll
        for (int w2 = 1; w2 < 8; w2++) {
            float4 b = sh[w2][lane];
            a.x += b.x; a.y += b.y; a.z += b.z; a.w += b.w;
        }
        red_add_v4(poolp + lane * 4, a.x, a.y, a.z, a.w);
    }
}

// ---------------- tiny MLP head: 384 -> 128 -> 64 -> 10 ----------------
__global__ __launch_bounds__(128) void k_mlp(
    const float* __restrict__ pool,
    const float* __restrict__ fw1, const float* __restrict__ fb1,
    const float* __restrict__ fw2, const float* __restrict__ fb2,
    const float* __restrict__ fw3, const float* __restrict__ fb3,
    float* __restrict__ out)
{
    __shared__ float p[3 * HDIM];
    __shared__ float h1[128];
    __shared__ float h2[64];
    int t = threadIdx.x;

    for (int i = t; i < 3 * HDIM; i += 128) p[i] = pool[i];
    __syncthreads();

    float s = fb1[t];
#pragma unroll 8
    for (int k = 0; k < 3 * HDIM; k++) s += p[k] * fw1[k * 128 + t];
    h1[t] = fmaxf(s, 0.0f);
    __syncthreads();

    if (t < 64) {
        float s2 = fb2[t];
#pragma unroll 8
        for (int k = 0; k < 128; k++) s2 += h1[k] * fw2[k * 64 + t];
        h2[t] = fmaxf(s2, 0.0f);
    }
    __syncthreads();

    if (t < 10) {
        float s3 = fb3[t];
#pragma unroll
        for (int k = 0; k < 64; k++) s3 += h2[k] * fw3[k * 10 + t];
        out[t] = s3;
    }
}

// ---------------- launch ----------------
extern "C" void kernel_launch(void* const* d_in, const int* in_sizes, int n_in,
                              void* d_out, int out_size)
{
    const float* x   = (const float*)d_in[0];
    const int*   ei  = (const int*)  d_in[1];
    const float* W1  = (const float*)d_in[2];
    const float* b1  = (const float*)d_in[3];
    const float* W2  = (const float*)d_in[4];
    const float* b2  = (const float*)d_in[5];
    const float* W3  = (const float*)d_in[6];
    const float* b3  = (const float*)d_in[7];
    const float* fw1 = (const float*)d_in[8];
    const float* fb1 = (const float*)d_in[9];
    const float* fw2 = (const float*)d_in[10];
    const float* fb2 = (const float*)d_in[11];
    const float* fw3 = (const float*)d_in[12];
    const float* fb3 = (const float*)d_in[13];

    const int N = in_sizes[0] / HDIM;
    const int E = in_sizes[1] / 2;
    const int* src = ei;
    const int* tgt = ei + E;

    int *cnt, *rowptr, *cur, *blk;
    int2 *epack;
    float *dis, *hw, *pool;
    __nv_bfloat16 *xh, *xl, *wh, *wl;
    cudaGetSymbolAddress((void**)&cnt,    g_cnt);
    cudaGetSymbolAddress((void**)&rowptr, g_rowptr);
    cudaGetSymbolAddress((void**)&cur,    g_cur);
    cudaGetSymbolAddress((void**)&epack,  g_epack);
    cudaGetSymbolAddress((void**)&blk,    g_blk);
    cudaGetSymbolAddress((void**)&dis,    g_dis);
    cudaGetSymbolAddress((void**)&hw,     g_hw);
    cudaGetSymbolAddress((void**)&xh,     g_xh);
    cudaGetSymbolAddress((void**)&xl,     g_xl);
    cudaGetSymbolAddress((void**)&wh,     g_wh);
    cudaGetSymbolAddress((void**)&wl,     g_wl);
    cudaGetSymbolAddress((void**)&pool,   g_pool);

    const int gemm_blocks = (N + TM - 1) / TM;
    const int NB = (N + 255) / 256;
    const int GATHER_BLOCKS = 1024;

    // ---- CSR build + input conversion (independent streams of work) ----
    k_setup<<<(N + 255) / 256, 256>>>(cnt, pool, N);
    k_hist <<<(E + 255) / 256, 256>>>(tgt, cnt, E);
    k_dis  <<<(N + 255) / 256, 256>>>(cnt, dis, N);
    k_scan1<<<NB, 256>>>(cnt, rowptr, blk, N);
    k_scan2<<<1, 256>>>(blk, NB);
    k_scan3<<<NB, 256>>>(rowptr, cur, blk, N, E);
    k_fill <<<(E + 255) / 256, 256>>>(src, tgt, dis, cur, epack, E);
    k_convX<<<(N * 32 + 255) / 256, 256>>>(x, xh, xl, N * 32);

    // ---- layer 1 ----
    k_convW <<<64, 256>>>(W1, wh, wl);
    k_gemm  <<<gemm_blocks, 256>>>(xh, xl, wh, wl, hw, N);
    k_gather<<<GATHER_BLOCKS, 256>>>(rowptr, epack, hw, b1, dis, xh, xl, 1, pool, N);

    // ---- layer 2 ----
    k_convW <<<64, 256>>>(W2, wh, wl);
    k_gemm  <<<gemm_blocks, 256>>>(xh, xl, wh, wl, hw, N);
    k_gather<<<GATHER_BLOCKS, 256>>>(rowptr, epack, hw, b2, dis, xh, xl, 1, pool + HDIM, N);

    // ---- layer 3 ----
    k_convW <<<64, 256>>>(W3, wh, wl);
    k_gemm  <<<gemm_blocks, 256>>>(xh, xl, wh, wl, hw, N);
    k_gather<<<GATHER_BLOCKS, 256>>>(rowptr, epack, hw, b3, dis, xh, xl, 0, pool + 2 * HDIM, N);

    k_mlp<<<1, 128>>>(pool, fw1, fb1, fw2, fb2, fw3, fb3, (float*)d_out);
}

// round 12
// speedup vs baseline: 1.9258x; 1.0701x over previous
#include <cuda_runtime.h>
#include <cuda_bf16.h>
#include <stdint.h>
#include <math.h>

#define MAXN 50000
#define MAXE 600000
#define HDIM 128

// ---------------- device scratch (no allocations allowed) ----------------
__device__ int   g_cnt[MAXN];
__device__ int   g_rowptr[MAXN + 1];
__device__ int   g_cur[MAXN];
__device__ int2  g_epack[MAXE];
__device__ int   g_blk[256];
__device__ float g_dis[MAXN];
__device__ float g_hw [MAXN * HDIM];               // GEMM output (fp32)
__device__ __nv_bfloat16 g_xh[MAXN * HDIM];        // layer input, hi plane
__device__ __nv_bfloat16 g_xl[MAXN * HDIM];        // layer input, lo plane
__device__ __nv_bfloat16 g_wh[3 * HDIM * HDIM];    // W^T hi planes [layer][n][k]
__device__ __nv_bfloat16 g_wl[3 * HDIM * HDIM];    // W^T lo planes
__device__ float g_pool[3 * HDIM];

__device__ __forceinline__ void red_add_v4(float* addr, float a, float b, float c, float d) {
    asm volatile("red.global.add.v4.f32 [%0], {%1, %2, %3, %4};"
                 :: "l"(addr), "f"(a), "f"(b), "f"(c), "f"(d) : "memory");
}

__device__ __forceinline__ void mma_bf16(float* c,
    uint32_t a0, uint32_t a1, uint32_t a2, uint32_t a3,
    uint32_t b0, uint32_t b1)
{
    asm volatile(
        "mma.sync.aligned.m16n8k16.row.col.f32.bf16.bf16.f32 "
        "{%0,%1,%2,%3}, {%4,%5,%6,%7}, {%8,%9}, {%0,%1,%2,%3};"
        : "+f"(c[0]), "+f"(c[1]), "+f"(c[2]), "+f"(c[3])
        : "r"(a0), "r"(a1), "r"(a2), "r"(a3), "r"(b0), "r"(b1));
}

__device__ __forceinline__ uint32_t pack_bf16x2(__nv_bfloat16 a, __nv_bfloat16 b) {
    return (uint32_t)__bfloat16_as_ushort(a) | ((uint32_t)__bfloat16_as_ushort(b) << 16);
}

__device__ __forceinline__ void cp_async16(void* dst, const void* src, int bytes) {
    uint32_t s = (uint32_t)__cvta_generic_to_shared(dst);
    asm volatile("cp.async.cg.shared.global [%0], [%1], 16, %2;"
                 :: "r"(s), "l"(src), "r"(bytes) : "memory");
}
#define CP_COMMIT() asm volatile("cp.async.commit_group;" ::: "memory")

// ---------------- setup ----------------
__global__ void k_setup(int* cnt, float* pool, int n) {
    int i = blockIdx.x * blockDim.x + threadIdx.x;
    if (i < 3 * HDIM) pool[i] = 0.0f;
    if (i < n) cnt[i] = 0;
}

__global__ void k_hist(const int* __restrict__ tgt, int* __restrict__ cnt, int e) {
    int i = blockIdx.x * blockDim.x + threadIdx.x;
    if (i < e) atomicAdd(&cnt[tgt[i]], 1);
}

// ---- scan level 1 (+ dis = rsqrt(deg+1) folded in) ----
__global__ void k_scan1(const int* __restrict__ cnt, int* __restrict__ rp,
                        int* __restrict__ blk, float* __restrict__ dis, int n) {
    __shared__ int sh[256];
    int t = threadIdx.x;
    int i = blockIdx.x * 256 + t;
    int v = (i < n) ? cnt[i] : 0;
    if (i < n) dis[i] = rsqrtf((float)(v + 1));
    sh[t] = v;
    __syncthreads();
    for (int off = 1; off < 256; off <<= 1) {
        int x = (t >= off) ? sh[t - off] : 0;
        __syncthreads();
        sh[t] += x;
        __syncthreads();
    }
    if (i < n) rp[i] = sh[t] - v;
    if (t == 255) blk[blockIdx.x] = sh[255];
}

__global__ void k_scan2(int* __restrict__ blk, int nb) {
    __shared__ int sh[256];
    int t = threadIdx.x;
    int v = (t < nb) ? blk[t] : 0;
    sh[t] = v;
    __syncthreads();
    for (int off = 1; off < 256; off <<= 1) {
        int x = (t >= off) ? sh[t - off] : 0;
        __syncthreads();
        sh[t] += x;
        __syncthreads();
    }
    if (t < nb) blk[t] = sh[t] - v;
}

__global__ void k_scan3(int* __restrict__ rp, int* __restrict__ cur,
                        const int* __restrict__ blk, int n, int e) {
    int i = blockIdx.x * blockDim.x + threadIdx.x;
    if (i < n) {
        int r = rp[i] + blk[i >> 8];
        rp[i]  = r;
        cur[i] = r;
        if (i == n - 1) rp[n] = e;
    }
}

__global__ void k_fill(const int* __restrict__ src, const int* __restrict__ tgt,
                       const float* __restrict__ dis,
                       int* __restrict__ cur, int2* __restrict__ epack, int e) {
    int i = blockIdx.x * blockDim.x + threadIdx.x;
    if (i < e) {
        int s = src[i];
        int t = tgt[i];
        int pos = atomicAdd(&cur[t], 1);
        epack[pos] = make_int2(s, __float_as_int(dis[s] * dis[t]));
    }
}

// ---------------- split-bf16 conversions ----------------
__global__ void k_convX(const float* __restrict__ x,
                        __nv_bfloat16* __restrict__ xh, __nv_bfloat16* __restrict__ xl,
                        int total4) {
    int i = blockIdx.x * blockDim.x + threadIdx.x;
    if (i >= total4) return;
    float4 v = *(const float4*)(x + (size_t)i * 4);
    __nv_bfloat16 hx = __float2bfloat16(v.x), hy = __float2bfloat16(v.y);
    __nv_bfloat16 hz = __float2bfloat16(v.z), hw = __float2bfloat16(v.w);
    uint2 ph, pl;
    ph.x = pack_bf16x2(hx, hy);
    ph.y = pack_bf16x2(hz, hw);
    pl.x = pack_bf16x2(__float2bfloat16(v.x - __bfloat162float(hx)),
                       __float2bfloat16(v.y - __bfloat162float(hy)));
    pl.y = pack_bf16x2(__float2bfloat16(v.z - __bfloat162float(hz)),
                       __float2bfloat16(v.w - __bfloat162float(hw)));
    *(uint2*)(xh + (size_t)i * 4) = ph;
    *(uint2*)(xl + (size_t)i * 4) = pl;
}

// all three W [k][n] -> transposed planes [layer][n][k]
__global__ void k_convW3(const float* __restrict__ W1, const float* __restrict__ W2,
                         const float* __restrict__ W3,
                         __nv_bfloat16* __restrict__ wh, __nv_bfloat16* __restrict__ wl) {
    int idx = blockIdx.x * blockDim.x + threadIdx.x;   // 0..49151
    int layer = idx >> 14;
    int r = idx & 16383;
    int k = r >> 7, n = r & 127;
    const float* W = (layer == 0) ? W1 : (layer == 1) ? W2 : W3;
    float f = W[r];
    __nv_bfloat16 h = __float2bfloat16(f);
    size_t o = (size_t)layer * HDIM * HDIM + n * HDIM + k;
    wh[o] = h;
    wl[o] = __float2bfloat16(f - __bfloat162float(h));
}

// ---------------- pipelined GEMM: HW = planes(A) @ planes(W) ----------------
// W planes (full K) resident in smem; A k-tiles double-buffered via cp.async.
// Block: 256 threads = 8 warps in 4(M) x 2(N); warp tile m32 x n64.
#define TM 128
#define KPAD_A 40
#define KPAD_B 136
// dynamic smem layout (bf16 elements):
//   AH: [2][128][40]  @ 0        (5120 per stage)
//   AL: [2][128][40]  @ 10240
//   BH: [128][136]    @ 20480
//   BL: [128][136]    @ 37888
#define SMEM_ELEMS 55296
#define AH_OFF(st) ((st) * 5120)
#define AL_OFF(st) (10240 + (st) * 5120)
#define BH_OFF     20480
#define BL_OFF     37888

__global__ __launch_bounds__(256, 2) void k_gemm(
    const __nv_bfloat16* __restrict__ Ahp, const __nv_bfloat16* __restrict__ Alp,
    const __nv_bfloat16* __restrict__ Bhp, const __nv_bfloat16* __restrict__ Blp,
    float* __restrict__ HW, int M)
{
    extern __shared__ __nv_bfloat16 sm[];

    const int tid  = threadIdx.x;
    const int lane = tid & 31;
    const int warp = tid >> 5;
    const int wm   = warp & 3;
    const int wn   = warp >> 2;
    const int g    = lane >> 2;
    const int tg   = lane & 3;
    const int row0 = blockIdx.x * TM;

    // ---- issue B (full K, both planes): 16 cp.async per thread ----
    {
#pragma unroll
        for (int it2 = 0; it2 < 8; it2++) {
            int i = tid + it2 * 256;        // 0..2047
            int r = i >> 4;
            int q = (i & 15) * 8;
            cp_async16(&sm[BH_OFF + r * KPAD_B + q], Bhp + (size_t)r * HDIM + q, 16);
            cp_async16(&sm[BL_OFF + r * KPAD_B + q], Blp + (size_t)r * HDIM + q, 16);
        }
    }
    // ---- issue A stage 0 (k-tile 0), same commit group as B -> group 0 ----
    {
#pragma unroll
        for (int it2 = 0; it2 < 2; it2++) {
            int i = tid + it2 * 256;        // 0..511
            int r = i >> 2;
            int q = (i & 3) * 8;
            int gr = row0 + r;
            int bytes = (gr < M) ? 16 : 0;
            int cr = (gr < M) ? gr : (M - 1);
            cp_async16(&sm[AH_OFF(0) + r * KPAD_A + q], Ahp + (size_t)cr * HDIM + 0 + q, bytes);
            cp_async16(&sm[AL_OFF(0) + r * KPAD_A + q], Alp + (size_t)cr * HDIM + 0 + q, bytes);
        }
    }
    CP_COMMIT();                            // group 0: B + A0
    // ---- issue A stage 1 (k-tile 1) -> group 1 ----
    {
#pragma unroll
        for (int it2 = 0; it2 < 2; it2++) {
            int i = tid + it2 * 256;
            int r = i >> 2;
            int q = (i & 3) * 8;
            int gr = row0 + r;
            int bytes = (gr < M) ? 16 : 0;
            int cr = (gr < M) ? gr : (M - 1);
            cp_async16(&sm[AH_OFF(1) + r * KPAD_A + q], Ahp + (size_t)cr * HDIM + 32 + q, bytes);
            cp_async16(&sm[AL_OFF(1) + r * KPAD_A + q], Alp + (size_t)cr * HDIM + 32 + q, bytes);
        }
    }
    CP_COMMIT();                            // group 1: A1

    float acc[2][8][4];
#pragma unroll
    for (int mt = 0; mt < 2; mt++)
#pragma unroll
        for (int nt = 0; nt < 8; nt++)
#pragma unroll
            for (int q = 0; q < 4; q++) acc[mt][nt][q] = 0.0f;

#pragma unroll
    for (int it = 0; it < 4; it++) {
        if (it < 3) { asm volatile("cp.async.wait_group 1;" ::: "memory"); }
        else        { asm volatile("cp.async.wait_group 0;" ::: "memory"); }
        __syncthreads();

        const int st = it & 1;
#pragma unroll
        for (int ks = 0; ks < 2; ks++) {
            const int kb  = ks * 16;            // within A tile
            const int kgb = it * 32 + ks * 16;  // global k for B
            uint32_t Ahf[2][4], Alf[2][4];
#pragma unroll
            for (int mt = 0; mt < 2; mt++) {
                int r = wm * 32 + mt * 16 + g;
                const __nv_bfloat16* ah0 = &sm[AH_OFF(st) + r * KPAD_A];
                const __nv_bfloat16* ah1 = &sm[AH_OFF(st) + (r + 8) * KPAD_A];
                const __nv_bfloat16* al0 = &sm[AL_OFF(st) + r * KPAD_A];
                const __nv_bfloat16* al1 = &sm[AL_OFF(st) + (r + 8) * KPAD_A];
                Ahf[mt][0] = *(const uint32_t*)(ah0 + kb + tg * 2);
                Ahf[mt][1] = *(const uint32_t*)(ah1 + kb + tg * 2);
                Ahf[mt][2] = *(const uint32_t*)(ah0 + kb + tg * 2 + 8);
                Ahf[mt][3] = *(const uint32_t*)(ah1 + kb + tg * 2 + 8);
                Alf[mt][0] = *(const uint32_t*)(al0 + kb + tg * 2);
                Alf[mt][1] = *(const uint32_t*)(al1 + kb + tg * 2);
                Alf[mt][2] = *(const uint32_t*)(al0 + kb + tg * 2 + 8);
                Alf[mt][3] = *(const uint32_t*)(al1 + kb + tg * 2 + 8);
            }
#pragma unroll
            for (int nt = 0; nt < 8; nt++) {
                int c = wn * 64 + nt * 8 + g;
                const __nv_bfloat16* bh = &sm[BH_OFF + c * KPAD_B + kgb];
                const __nv_bfloat16* bl = &sm[BL_OFF + c * KPAD_B + kgb];
                uint32_t bh0 = *(const uint32_t*)(bh + tg * 2);
                uint32_t bh1 = *(const uint32_t*)(bh + tg * 2 + 8);
                uint32_t bl0 = *(const uint32_t*)(bl + tg * 2);
                uint32_t bl1 = *(const uint32_t*)(bl + tg * 2 + 8);
#pragma unroll
                for (int mt = 0; mt < 2; mt++) {
                    mma_bf16(acc[mt][nt], Ahf[mt][0], Ahf[mt][1], Ahf[mt][2], Ahf[mt][3], bh0, bh1);
                    mma_bf16(acc[mt][nt], Ahf[mt][0], Ahf[mt][1], Ahf[mt][2], Ahf[mt][3], bl0, bl1);
                    mma_bf16(acc[mt][nt], Alf[mt][0], Alf[mt][1], Alf[mt][2], Alf[mt][3], bh0, bh1);
                }
            }
        }
        __syncthreads();

        // refill the stage just consumed with k-tile it+2
        if (it + 2 < 4) {
            const int kt = (it + 2) * 32;
#pragma unroll
            for (int it2 = 0; it2 < 2; it2++) {
                int i = tid + it2 * 256;
                int r = i >> 2;
                int q = (i & 3) * 8;
                int gr = row0 + r;
                int bytes = (gr < M) ? 16 : 0;
                int cr = (gr < M) ? gr : (M - 1);
                cp_async16(&sm[AH_OFF(st) + r * KPAD_A + q], Ahp + (size_t)cr * HDIM + kt + q, bytes);
                cp_async16(&sm[AL_OFF(st) + r * KPAD_A + q], Alp + (size_t)cr * HDIM + kt + q, bytes);
            }
            CP_COMMIT();
        }
    }

#pragma unroll
    for (int mt = 0; mt < 2; mt++) {
        int r = row0 + wm * 32 + mt * 16 + g;
#pragma unroll
        for (int nt = 0; nt < 8; nt++) {
            int c = wn * 64 + nt * 8 + tg * 2;
            if (r < M)
                *(float2*)(HW + (size_t)r * HDIM + c) =
                    make_float2(acc[mt][nt][0], acc[mt][nt][1]);
            if (r + 8 < M)
                *(float2*)(HW + (size_t)(r + 8) * HDIM + c) =
                    make_float2(acc[mt][nt][2], acc[mt][nt][3]);
        }
    }
}

// ---------------- CSR gather + self loop + bias + relu-pool + bf16 plane output ----
__global__ __launch_bounds__(256) void k_gather(
    const int* __restrict__ rowptr, const int2* __restrict__ epack,
    const float* __restrict__ hw,
    const float* __restrict__ bias, const float* __restrict__ dis,
    __nv_bfloat16* __restrict__ outh, __nv_bfloat16* __restrict__ outl,
    int writePlanes, float* __restrict__ poolp, int n)
{
    const int lane  = threadIdx.x & 31;
    const int wid   = (blockIdx.x * blockDim.x + threadIdx.x) >> 5;
    const int nwarp = (gridDim.x * blockDim.x) >> 5;

    float4 bb = *(const float4*)(bias + lane * 4);
    float4 pacc = make_float4(0.f, 0.f, 0.f, 0.f);

    for (int i = wid; i < n; i += nwarp) {
        float d  = dis[i];
        float d2 = d * d;
        float4 h = *(const float4*)(hw + (size_t)i * HDIM + lane * 4);
        float4 a0;
        a0.x = bb.x + d2 * h.x; a0.y = bb.y + d2 * h.y;
        a0.z = bb.z + d2 * h.z; a0.w = bb.w + d2 * h.w;

        int e0 = rowptr[i];
        int e1 = rowptr[i + 1];
        for (int base = e0; base < e1; base += 32) {
            int m = e1 - base;
            if (m > 32) m = 32;
            int2 p = make_int2(0, 0);
            if (base + lane < e1) p = __ldg(&epack[base + lane]);
            #pragma unroll 4
            for (int j = 0; j < m; j++) {
                int   s = __shfl_sync(0xffffffffu, p.x, j);
                float w = __int_as_float(__shfl_sync(0xffffffffu, p.y, j));
                float4 v = *(const float4*)(hw + (size_t)s * HDIM + lane * 4);
                a0.x += w * v.x; a0.y += w * v.y;
                a0.z += w * v.z; a0.w += w * v.w;
            }
        }

        float rx = fmaxf(a0.x, 0.f), ry = fmaxf(a0.y, 0.f);
        float rz = fmaxf(a0.z, 0.f), rw = fmaxf(a0.w, 0.f);
        pacc.x += rx; pacc.y += ry; pacc.z += rz; pacc.w += rw;

        if (writePlanes) {
            __nv_bfloat16 hx = __float2bfloat16(rx), hy = __float2bfloat16(ry);
            __nv_bfloat16 hz = __float2bfloat16(rz), hw2 = __float2bfloat16(rw);
            uint2 ph, pl;
            ph.x = pack_bf16x2(hx, hy);
            ph.y = pack_bf16x2(hz, hw2);
            pl.x = pack_bf16x2(__float2bfloat16(rx - __bfloat162float(hx)),
                               __float2bfloat16(ry - __bfloat162float(hy)));
            pl.y = pack_bf16x2(__float2bfloat16(rz - __bfloat162float(hz)),
                               __float2bfloat16(rw - __bfloat162float(hw2)));
            *(uint2*)(outh + (size_t)i * HDIM + lane * 4) = ph;
            *(uint2*)(outl + (size_t)i * HDIM + lane * 4) = pl;
        }
    }

    __shared__ float4 sh[8][32];
    int warp = threadIdx.x >> 5;
    sh[warp][lane] = pacc;
    __syncthreads();
    if (warp == 0) {
        float4 a = sh[0][lane];
#pragma unroll
        for (int w2 = 1; w2 < 8; w2++) {
            float4 b = sh[w2][lane];
            a.x += b.x; a.y += b.y; a.z += b.z; a.w += b.w;
        }
        red_add_v4(poolp + lane * 4, a.x, a.y, a.z, a.w);
    }
}

// ---------------- tiny MLP head: 384 -> 128 -> 64 -> 10 ----------------
__global__ __launch_bounds__(128) void k_mlp(
    const float* __restrict__ pool,
    const float* __restrict__ fw1, const float* __restrict__ fb1,
    const float* __restrict__ fw2, const float* __restrict__ fb2,
    const float* __restrict__ fw3, const float* __restrict__ fb3,
    float* __restrict__ out)
{
    __shared__ float p[3 * HDIM];
    __shared__ float h1[128];
    __shared__ float h2[64];
    int t = threadIdx.x;

    for (int i = t; i < 3 * HDIM; i += 128) p[i] = pool[i];
    __syncthreads();

    float s = fb1[t];
#pragma unroll 8
    for (int k = 0; k < 3 * HDIM; k++) s += p[k] * fw1[k * 128 + t];
    h1[t] = fmaxf(s, 0.0f);
    __syncthreads();

    if (t < 64) {
        float s2 = fb2[t];
#pragma unroll 8
        for (int k = 0; k < 128; k++) s2 += h1[k] * fw2[k * 64 + t];
        h2[t] = fmaxf(s2, 0.0f);
    }
    __syncthreads();

    if (t < 10) {
        float s3 = fb3[t];
#pragma unroll
        for (int k = 0; k < 64; k++) s3 += h2[k] * fw3[k * 10 + t];
        out[t] = s3;
    }
}

// ---------------- launch ----------------
extern "C" void kernel_launch(void* const* d_in, const int* in_sizes, int n_in,
                              void* d_out, int out_size)
{
    const float* x   = (const float*)d_in[0];
    const int*   ei  = (const int*)  d_in[1];
    const float* W1  = (const float*)d_in[2];
    const float* b1  = (const float*)d_in[3];
    const float* W2  = (const float*)d_in[4];
    const float* b2  = (const float*)d_in[5];
    const float* W3  = (const float*)d_in[6];
    const float* b3  = (const float*)d_in[7];
    const float* fw1 = (const float*)d_in[8];
    const float* fb1 = (const float*)d_in[9];
    const float* fw2 = (const float*)d_in[10];
    const float* fb2 = (const float*)d_in[11];
    const float* fw3 = (const float*)d_in[12];
    const float* fb3 = (const float*)d_in[13];

    const int N = in_sizes[0] / HDIM;
    const int E = in_sizes[1] / 2;
    const int* src = ei;
    const int* tgt = ei + E;

    int *cnt, *rowptr, *cur, *blk;
    int2 *epack;
    float *dis, *hw, *pool;
    __nv_bfloat16 *xh, *xl, *wh, *wl;
    cudaGetSymbolAddress((void**)&cnt,    g_cnt);
    cudaGetSymbolAddress((void**)&rowptr, g_rowptr);
    cudaGetSymbolAddress((void**)&cur,    g_cur);
    cudaGetSymbolAddress((void**)&epack,  g_epack);
    cudaGetSymbolAddress((void**)&blk,    g_blk);
    cudaGetSymbolAddress((void**)&dis,    g_dis);
    cudaGetSymbolAddress((void**)&hw,     g_hw);
    cudaGetSymbolAddress((void**)&xh,     g_xh);
    cudaGetSymbolAddress((void**)&xl,     g_xl);
    cudaGetSymbolAddress((void**)&wh,     g_wh);
    cudaGetSymbolAddress((void**)&wl,     g_wl);
    cudaGetSymbolAddress((void**)&pool,   g_pool);

    const int gemm_blocks = (N + TM - 1) / TM;
    const int NB = (N + 255) / 256;
    const int GATHER_BLOCKS = 1024;
    const size_t GEMM_SMEM = SMEM_ELEMS * sizeof(__nv_bfloat16);   // 110592 B

    static int smem_configured = 0;
    if (!smem_configured) {
        cudaFuncSetAttribute(k_gemm, cudaFuncAttributeMaxDynamicSharedMemorySize,
                             (int)GEMM_SMEM);
        smem_configured = 1;
    }

    const size_t WSTRIDE = (size_t)HDIM * HDIM;

    // ---- CSR build + conversions ----
    k_setup <<<(N + 255) / 256, 256>>>(cnt, pool, N);
    k_hist  <<<(E + 255) / 256, 256>>>(tgt, cnt, E);
    k_convX <<<(N * 32 + 255) / 256, 256>>>(x, xh, xl, N * 32);
    k_convW3<<<192, 256>>>(W1, W2, W3, wh, wl);
    k_scan1 <<<NB, 256>>>(cnt, rowptr, blk, dis, N);
    k_scan2 <<<1, 256>>>(blk, NB);
    k_scan3 <<<NB, 256>>>(rowptr, cur, blk, N, E);
    k_fill  <<<(E + 255) / 256, 256>>>(src, tgt, dis, cur, epack, E);

    // ---- layer 1 ----
    k_gemm  <<<gemm_blocks, 256, GEMM_SMEM>>>(xh, xl, wh, wl, hw, N);
    k_gather<<<GATHER_BLOCKS, 256>>>(rowptr, epack, hw, b1, dis, xh, xl, 1, pool, N);

    // ---- layer 2 ----
    k_gemm  <<<gemm_blocks, 256, GEMM_SMEM>>>(xh, xl, wh + WSTRIDE, wl + WSTRIDE, hw, N);
    k_gather<<<GATHER_BLOCKS, 256>>>(rowptr, epack, hw, b2, dis, xh, xl, 1, pool + HDIM, N);

    // ---- layer 3 ----
    k_gemm  <<<gemm_blocks, 256, GEMM_SMEM>>>(xh, xl, wh + 2 * WSTRIDE, wl + 2 * WSTRIDE, hw, N);
    k_gather<<<GATHER_BLOCKS, 256>>>(rowptr, epack, hw, b3, dis, xh, xl, 0, pool + 2 * HDIM, N);

    k_mlp<<<1, 128>>>(pool, fw1, fb1, fw2, fb2, fw3, fb3, (float*)d_out);
}

// round 14
// speedup vs baseline: 1.9810x; 1.0286x over previous
#include <cuda_runtime.h>
#include <cuda_bf16.h>
#include <stdint.h>
#include <math.h>

#define MAXN 50000
#define MAXE 600000
#define HDIM 128

// ---------------- device scratch (no allocations allowed) ----------------
__device__ int   g_cnt[MAXN];                      // zero at load; re-zeroed each launch
__device__ int   g_rowptr[MAXN + 1];
__device__ int   g_cur[MAXN];
__device__ int2  g_epack[MAXE];
__device__ int   g_blk[256];
__device__ float g_dis[MAXN];
__device__ float g_hw [MAXN * HDIM];               // GEMM output (fp32)
__device__ __nv_bfloat16 g_xh[MAXN * HDIM];        // layer input, hi plane
__device__ __nv_bfloat16 g_xl[MAXN * HDIM];        // layer input, lo plane
__device__ __nv_bfloat16 g_wh[3 * HDIM * HDIM];    // W^T hi planes [layer][n][k]
__device__ __nv_bfloat16 g_wl[3 * HDIM * HDIM];    // W^T lo planes
__device__ float g_pool[3 * HDIM];                 // zero at load; re-zeroed by k_mlp

__device__ __forceinline__ void red_add_v4(float* addr, float a, float b, float c, float d) {
    asm volatile("red.global.add.v4.f32 [%0], {%1, %2, %3, %4};"
                 :: "l"(addr), "f"(a), "f"(b), "f"(c), "f"(d) : "memory");
}

__device__ __forceinline__ void mma_bf16(float* c,
    uint32_t a0, uint32_t a1, uint32_t a2, uint32_t a3,
    uint32_t b0, uint32_t b1)
{
    asm volatile(
        "mma.sync.aligned.m16n8k16.row.col.f32.bf16.bf16.f32 "
        "{%0,%1,%2,%3}, {%4,%5,%6,%7}, {%8,%9}, {%0,%1,%2,%3};"
        : "+f"(c[0]), "+f"(c[1]), "+f"(c[2]), "+f"(c[3])
        : "r"(a0), "r"(a1), "r"(a2), "r"(a3), "r"(b0), "r"(b1));
}

__device__ __forceinline__ void ldsm_x4(uint32_t& d0, uint32_t& d1, uint32_t& d2, uint32_t& d3,
                                        uint32_t addr) {
    asm volatile("ldmatrix.sync.aligned.m8n8.x4.shared.b16 {%0,%1,%2,%3}, [%4];"
                 : "=r"(d0), "=r"(d1), "=r"(d2), "=r"(d3) : "r"(addr));
}

__device__ __forceinline__ uint32_t pack_bf16x2(__nv_bfloat16 a, __nv_bfloat16 b) {
    return (uint32_t)__bfloat16_as_ushort(a) | ((uint32_t)__bfloat16_as_ushort(b) << 16);
}

__device__ __forceinline__ void cp_async16(void* dst, const void* src, int bytes) {
    uint32_t s = (uint32_t)__cvta_generic_to_shared(dst);
    asm volatile("cp.async.cg.shared.global [%0], [%1], 16, %2;"
                 :: "r"(s), "l"(src), "r"(bytes) : "memory");
}
#define CP_COMMIT() asm volatile("cp.async.commit_group;" ::: "memory")

// ---------------- histogram (cnt is pre-zeroed: load-time / previous launch) -----
__global__ void k_hist(const int* __restrict__ tgt, int* __restrict__ cnt, int e) {
    int i = blockIdx.x * blockDim.x + threadIdx.x;
    if (i < e) atomicAdd(&cnt[tgt[i]], 1);
}

// ---------------- fused conversions: x planes + all 3 W planes ----------------
__global__ void k_conv(const float* __restrict__ x,
                       __nv_bfloat16* __restrict__ xh, __nv_bfloat16* __restrict__ xl,
                       int total4, int nbX,
                       const float* __restrict__ W1, const float* __restrict__ W2,
                       const float* __restrict__ W3,
                       __nv_bfloat16* __restrict__ wh, __nv_bfloat16* __restrict__ wl) {
    if (blockIdx.x < nbX) {
        int i = blockIdx.x * blockDim.x + threadIdx.x;
        if (i >= total4) return;
        float4 v = *(const float4*)(x + (size_t)i * 4);
        __nv_bfloat16 hx = __float2bfloat16(v.x), hy = __float2bfloat16(v.y);
        __nv_bfloat16 hz = __float2bfloat16(v.z), hw = __float2bfloat16(v.w);
        uint2 ph, pl;
        ph.x = pack_bf16x2(hx, hy);
        ph.y = pack_bf16x2(hz, hw);
        pl.x = pack_bf16x2(__float2bfloat16(v.x - __bfloat162float(hx)),
                           __float2bfloat16(v.y - __bfloat162float(hy)));
        pl.y = pack_bf16x2(__float2bfloat16(v.z - __bfloat162float(hz)),
                           __float2bfloat16(v.w - __bfloat162float(hw)));
        *(uint2*)(xh + (size_t)i * 4) = ph;
        *(uint2*)(xl + (size_t)i * 4) = pl;
    } else {
        int idx = (blockIdx.x - nbX) * blockDim.x + threadIdx.x;   // 0..49151
        if (idx >= 3 * HDIM * HDIM) return;
        int layer = idx >> 14;
        int r = idx & 16383;
        int k = r >> 7, n = r & 127;
        const float* W = (layer == 0) ? W1 : (layer == 1) ? W2 : W3;
        float f = W[r];
        __nv_bfloat16 h = __float2bfloat16(f);
        size_t o = (size_t)layer * HDIM * HDIM + n * HDIM + k;
        wh[o] = h;
        wl[o] = __float2bfloat16(f - __bfloat162float(h));
    }
}

// ---- scan level 1 (+ dis = rsqrt(deg+1) folded in) ----
__global__ void k_scan1(const int* __restrict__ cnt, int* __restrict__ rp,
                        int* __restrict__ blk, float* __restrict__ dis, int n) {
    __shared__ int sh[256];
    int t = threadIdx.x;
    int i = blockIdx.x * 256 + t;
    int v = (i < n) ? cnt[i] : 0;
    if (i < n) dis[i] = rsqrtf((float)(v + 1));
    sh[t] = v;
    __syncthreads();
    for (int off = 1; off < 256; off <<= 1) {
        int x = (t >= off) ? sh[t - off] : 0;
        __syncthreads();
        sh[t] += x;
        __syncthreads();
    }
    if (i < n) rp[i] = sh[t] - v;
    if (t == 255) blk[blockIdx.x] = sh[255];
}

__global__ void k_scan2(int* __restrict__ blk, int nb) {
    __shared__ int sh[256];
    int t = threadIdx.x;
    int v = (t < nb) ? blk[t] : 0;
    sh[t] = v;
    __syncthreads();
    for (int off = 1; off < 256; off <<= 1) {
        int x = (t >= off) ? sh[t - off] : 0;
        __syncthreads();
        sh[t] += x;
        __syncthreads();
    }
    if (t < nb) blk[t] = sh[t] - v;
}

__global__ void k_scan3(int* __restrict__ rp, int* __restrict__ cur,
                        const int* __restrict__ blk, int n, int e) {
    int i = blockIdx.x * blockDim.x + threadIdx.x;
    if (i < n) {
        int r = rp[i] + blk[i >> 8];
        rp[i]  = r;
        cur[i] = r;
        if (i == n - 1) rp[n] = e;
    }
}

__global__ void k_fill(const int* __restrict__ src, const int* __restrict__ tgt,
                       const float* __restrict__ dis,
                       int* __restrict__ cur, int2* __restrict__ epack, int e) {
    int i = blockIdx.x * blockDim.x + threadIdx.x;
    if (i < e) {
        int s = src[i];
        int t = tgt[i];
        int pos = atomicAdd(&cur[t], 1);
        epack[pos] = make_int2(s, __float_as_int(dis[s] * dis[t]));
    }
}

// ---------------- pipelined GEMM with ldmatrix fragment loads ----------------
#define TM 128
#define KPAD_A 40
#define KPAD_B 136
#define SMEM_ELEMS 55296
#define AH_OFF(st) ((st) * 5120)
#define AL_OFF(st) (10240 + (st) * 5120)
#define BH_OFF     20480
#define BL_OFF     37888

__global__ __launch_bounds__(256, 2) void k_gemm(
    const __nv_bfloat16* __restrict__ Ahp, const __nv_bfloat16* __restrict__ Alp,
    const __nv_bfloat16* __restrict__ Bhp, const __nv_bfloat16* __restrict__ Blp,
    float* __restrict__ HW, int M)
{
    extern __shared__ __nv_bfloat16 sm[];
    const uint32_t sbase = (uint32_t)__cvta_generic_to_shared(sm);

    const int tid  = threadIdx.x;
    const int lane = tid & 31;
    const int warp = tid >> 5;
    const int wm   = warp & 3;
    const int wn   = warp >> 2;
    const int g    = lane >> 2;
    const int tg   = lane & 3;
    const int row0 = blockIdx.x * TM;

    // per-lane ldmatrix address components
    const int rowA  = lane & 15;                 // row within 16-row fragment
    const int koffA = (lane >> 4) * 8;           // k-half select
    const int nrowB = lane & 7;
    const int khB   = ((lane >> 3) & 1) * 8;
    const int plB   = (lane >> 4) ? BL_OFF : BH_OFF;
    // element offsets (add stage/mt/kb/nt terms later)
    const int aOffBase = (wm * 32 + rowA) * KPAD_A + koffA;
    const int bOffBase = plB + (wn * 64 + nrowB) * KPAD_B + khB;

    // ---- issue B (full K, both planes) ----
#pragma unroll
    for (int it2 = 0; it2 < 8; it2++) {
        int i = tid + it2 * 256;
        int r = i >> 4;
        int q = (i & 15) * 8;
        cp_async16(&sm[BH_OFF + r * KPAD_B + q], Bhp + (size_t)r * HDIM + q, 16);
        cp_async16(&sm[BL_OFF + r * KPAD_B + q], Blp + (size_t)r * HDIM + q, 16);
    }
    // ---- A stage 0 ----
#pragma unroll
    for (int it2 = 0; it2 < 2; it2++) {
        int i = tid + it2 * 256;
        int r = i >> 2;
        int q = (i & 3) * 8;
        int gr = row0 + r;
        int bytes = (gr < M) ? 16 : 0;
        int cr = (gr < M) ? gr : (M - 1);
        cp_async16(&sm[AH_OFF(0) + r * KPAD_A + q], Ahp + (size_t)cr * HDIM + q, bytes);
        cp_async16(&sm[AL_OFF(0) + r * KPAD_A + q], Alp + (size_t)cr * HDIM + q, bytes);
    }
    CP_COMMIT();
    // ---- A stage 1 ----
#pragma unroll
    for (int it2 = 0; it2 < 2; it2++) {
        int i = tid + it2 * 256;
        int r = i >> 2;
        int q = (i & 3) * 8;
        int gr = row0 + r;
        int bytes = (gr < M) ? 16 : 0;
        int cr = (gr < M) ? gr : (M - 1);
        cp_async16(&sm[AH_OFF(1) + r * KPAD_A + q], Ahp + (size_t)cr * HDIM + 32 + q, bytes);
        cp_async16(&sm[AL_OFF(1) + r * KPAD_A + q], Alp + (size_t)cr * HDIM + 32 + q, bytes);
    }
    CP_COMMIT();

    float acc[2][8][4];
#pragma unroll
    for (int mt = 0; mt < 2; mt++)
#pragma unroll
        for (int nt = 0; nt < 8; nt++)
#pragma unroll
            for (int q = 0; q < 4; q++) acc[mt][nt][q] = 0.0f;

#pragma unroll
    for (int it = 0; it < 4; it++) {
        if (it < 3) { asm volatile("cp.async.wait_group 1;" ::: "memory"); }
        else        { asm volatile("cp.async.wait_group 0;" ::: "memory"); }
        __syncthreads();

        const int st = it & 1;
#pragma unroll
        for (int ks = 0; ks < 2; ks++) {
            const int kb  = ks * 16;
            const int kgb = it * 32 + ks * 16;
            uint32_t Ahf[2][4], Alf[2][4];
#pragma unroll
            for (int mt = 0; mt < 2; mt++) {
                uint32_t ah = sbase + 2u * (AH_OFF(st) + aOffBase + mt * 16 * KPAD_A + kb);
                uint32_t al = sbase + 2u * (AL_OFF(st) + aOffBase + mt * 16 * KPAD_A + kb);
                ldsm_x4(Ahf[mt][0], Ahf[mt][1], Ahf[mt][2], Ahf[mt][3], ah);
                ldsm_x4(Alf[mt][0], Alf[mt][1], Alf[mt][2], Alf[mt][3], al);
            }
#pragma unroll
            for (int nt = 0; nt < 8; nt++) {
                uint32_t ba = sbase + 2u * (bOffBase + nt * 8 * KPAD_B + kgb);
                uint32_t bh0, bh1, bl0, bl1;
                ldsm_x4(bh0, bh1, bl0, bl1, ba);
#pragma unroll
                for (int mt = 0; mt < 2; mt++) {
                    mma_bf16(acc[mt][nt], Ahf[mt][0], Ahf[mt][1], Ahf[mt][2], Ahf[mt][3], bh0, bh1);
                    mma_bf16(acc[mt][nt], Ahf[mt][0], Ahf[mt][1], Ahf[mt][2], Ahf[mt][3], bl0, bl1);
                    mma_bf16(acc[mt][nt], Alf[mt][0], Alf[mt][1], Alf[mt][2], Alf[mt][3], bh0, bh1);
                }
            }
        }
        __syncthreads();

        if (it + 2 < 4) {
            const int kt = (it + 2) * 32;
#pragma unroll
            for (int it2 = 0; it2 < 2; it2++) {
                int i = tid + it2 * 256;
                int r = i >> 2;
                int q = (i & 3) * 8;
                int gr = row0 + r;
                int bytes = (gr < M) ? 16 : 0;
                int cr = (gr < M) ? gr : (M - 1);
                cp_async16(&sm[AH_OFF(st) + r * KPAD_A + q], Ahp + (size_t)cr * HDIM + kt + q, bytes);
                cp_async16(&sm[AL_OFF(st) + r * KPAD_A + q], Alp + (size_t)cr * HDIM + kt + q, bytes);
            }
            CP_COMMIT();
        }
    }

#pragma unroll
    for (int mt = 0; mt < 2; mt++) {
        int r = row0 + wm * 32 + mt * 16 + g;
#pragma unroll
        for (int nt = 0; nt < 8; nt++) {
            int c = wn * 64 + nt * 8 + tg * 2;
            if (r < M)
                *(float2*)(HW + (size_t)r * HDIM + c) =
                    make_float2(acc[mt][nt][0], acc[mt][nt][1]);
            if (r + 8 < M)
                *(float2*)(HW + (size_t)(r + 8) * HDIM + c) =
                    make_float2(acc[mt][nt][2], acc[mt][nt][3]);
        }
    }
}

// ---------------- CSR gather + self loop + bias + relu-pool + plane output -------
__global__ __launch_bounds__(256) void k_gather(
    const int* __restrict__ rowptr, const int2* __restrict__ epack,
    const float* __restrict__ hw,
    const float* __restrict__ bias, const float* __restrict__ dis,
    __nv_bfloat16* __restrict__ outh, __nv_bfloat16* __restrict__ outl,
    int writePlanes, int* __restrict__ cntZero,
    float* __restrict__ poolp, int n)
{
    const int lane  = threadIdx.x & 31;
    const int wid   = (blockIdx.x * blockDim.x + threadIdx.x) >> 5;
    const int nwarp = (gridDim.x * blockDim.x) >> 5;

    float4 bb = *(const float4*)(bias + lane * 4);
    float4 pacc = make_float4(0.f, 0.f, 0.f, 0.f);

    for (int i = wid; i < n; i += nwarp) {
        if (cntZero && lane == 0) cntZero[i] = 0;   // reset for next launch
        float d  = dis[i];
        float d2 = d * d;
        float4 h = *(const float4*)(hw + (size_t)i * HDIM + lane * 4);
        float4 a0;
        a0.x = bb.x + d2 * h.x; a0.y = bb.y + d2 * h.y;
        a0.z = bb.z + d2 * h.z; a0.w = bb.w + d2 * h.w;

        int e0 = rowptr[i];
        int e1 = rowptr[i + 1];
        for (int base = e0; base < e1; base += 32) {
            int m = e1 - base;
            if (m > 32) m = 32;
            int2 p = make_int2(0, 0);
            if (base + lane < e1) p = __ldg(&epack[base + lane]);
            #pragma unroll 4
            for (int j = 0; j < m; j++) {
                int   s = __shfl_sync(0xffffffffu, p.x, j);
                float w = __int_as_float(__shfl_sync(0xffffffffu, p.y, j));
                float4 v = *(const float4*)(hw + (size_t)s * HDIM + lane * 4);
                a0.x += w * v.x; a0.y += w * v.y;
                a0.z += w * v.z; a0.w += w * v.w;
            }
        }

        float rx = fmaxf(a0.x, 0.f), ry = fmaxf(a0.y, 0.f);
        float rz = fmaxf(a0.z, 0.f), rw = fmaxf(a0.w, 0.f);
        pacc.x += rx; pacc.y += ry; pacc.z += rz; pacc.w += rw;

        if (writePlanes) {
            __nv_bfloat16 hx = __float2bfloat16(rx), hy = __float2bfloat16(ry);
            __nv_bfloat16 hz = __float2bfloat16(rz), hw2 = __float2bfloat16(rw);
            uint2 ph, pl;
            ph.x = pack_bf16x2(hx, hy);
            ph.y = pack_bf16x2(hz, hw2);
            pl.x = pack_bf16x2(__float2bfloat16(rx - __bfloat162float(hx)),
                               __float2bfloat16(ry - __bfloat162float(hy)));
            pl.y = pack_bf16x2(__float2bfloat16(rz - __bfloat162float(hz)),
                               __float2bfloat16(rw - __bfloat162float(hw2)));
            *(uint2*)(outh + (size_t)i * HDIM + lane * 4) = ph;
            *(uint2*)(outl + (size_t)i * HDIM + lane * 4) = pl;
        }
    }

    __shared__ float4 sh[8][32];
    int warp = threadIdx.x >> 5;
    sh[warp][lane] = pacc;
    __syncthreads();
    if (warp == 0) {
        float4 a = sh[0][lane];
#pragma unroll
        for (int w2 = 1; w2 < 8; w2++) {
            float4 b = sh[w2][lane];
            a.x += b.x; a.y += b.y; a.z += b.z; a.w += b.w;
        }
        red_add_v4(poolp + lane * 4, a.x, a.y, a.z, a.w);
    }
}

// ---------------- tiny MLP head: 384 -> 128 -> 64 -> 10 (re-zeroes pool) --------
__global__ __launch_bounds__(128) void k_mlp(
    float* __restrict__ pool,
    const float* __restrict__ fw1, const float* __restrict__ fb1,
    const float* __restrict__ fw2, const float* __restrict__ fb2,
    const float* __restrict__ fw3, const float* __restrict__ fb3,
    float* __restrict__ out)
{
    __shared__ float p[3 * HDIM];
    __shared__ float h1[128];
    __shared__ float h2[64];
    int t = threadIdx.x;

    for (int i = t; i < 3 * HDIM; i += 128) p[i] = pool[i];
    __syncthreads();
    for (int i = t; i < 3 * HDIM; i += 128) pool[i] = 0.0f;  // reset for next launch

    float s = fb1[t];
#pragma unroll 8
    for (int k = 0; k < 3 * HDIM; k++) s += p[k] * fw1[k * 128 + t];
    h1[t] = fmaxf(s, 0.0f);
    __syncthreads();

    if (t < 64) {
        float s2 = fb2[t];
#pragma unroll 8
        for (int k = 0; k < 128; k++) s2 += h1[k] * fw2[k * 64 + t];
        h2[t] = fmaxf(s2, 0.0f);
    }
    __syncthreads();

    if (t < 10) {
        float s3 = fb3[t];
#pragma unroll
        for (int k = 0; k < 64; k++) s3 += h2[k] * fw3[k * 10 + t];
        out[t] = s3;
    }
}

// ---------------- launch ----------------
extern "C" void kernel_launch(void* const* d_in, const int* in_sizes, int n_in,
                              void* d_out, int out_size)
{
    const float* x   = (const float*)d_in[0];
    const int*   ei  = (const int*)  d_in[1];
    const float* W1  = (const float*)d_in[2];
    const float* b1  = (const float*)d_in[3];
    const float* W2  = (const float*)d_in[4];
    const float* b2  = (const float*)d_in[5];
    const float* W3  = (const float*)d_in[6];
    const float* b3  = (const float*)d_in[7];
    const float* fw1 = (const float*)d_in[8];
    const float* fb1 = (const float*)d_in[9];
    const float* fw2 = (const float*)d_in[10];
    const float* fb2 = (const float*)d_in[11];
    const float* fw3 = (const float*)d_in[12];
    const float* fb3 = (const float*)d_in[13];

    const int N = in_sizes[0] / HDIM;
    const int E = in_sizes[1] / 2;
    const int* src = ei;
    const int* tgt = ei + E;

    int *cnt, *rowptr, *cur, *blk;
    int2 *epack;
    float *dis, *hw, *pool;
    __nv_bfloat16 *xh, *xl, *wh, *wl;
    cudaGetSymbolAddress((void**)&cnt,    g_cnt);
    cudaGetSymbolAddress((void**)&rowptr, g_rowptr);
    cudaGetSymbolAddress((void**)&cur,    g_cur);
    cudaGetSymbolAddress((void**)&epack,  g_epack);
    cudaGetSymbolAddress((void**)&blk,    g_blk);
    cudaGetSymbolAddress((void**)&dis,    g_dis);
    cudaGetSymbolAddress((void**)&hw,     g_hw);
    cudaGetSymbolAddress((void**)&xh,     g_xh);
    cudaGetSymbolAddress((void**)&xl,     g_xl);
    cudaGetSymbolAddress((void**)&wh,     g_wh);
    cudaGetSymbolAddress((void**)&wl,     g_wl);
    cudaGetSymbolAddress((void**)&pool,   g_pool);

    const int gemm_blocks = (N + TM - 1) / TM;
    const int NB = (N + 255) / 256;
    const int GATHER_BLOCKS = 1024;
    const size_t GEMM_SMEM = SMEM_ELEMS * sizeof(__nv_bfloat16);

    static int smem_configured = 0;
    if (!smem_configured) {
        cudaFuncSetAttribute(k_gemm, cudaFuncAttributeMaxDynamicSharedMemorySize,
                             (int)GEMM_SMEM);
        smem_configured = 1;
    }

    const size_t WSTRIDE = (size_t)HDIM * HDIM;
    const int nbX = (N * 32 + 255) / 256;

    // ---- CSR build + conversions (cnt pre-zeroed by prior launch / load) ----
    k_hist <<<(E + 255) / 256, 256>>>(tgt, cnt, E);
    k_conv <<<nbX + 192, 256>>>(x, xh, xl, N * 32, nbX, W1, W2, W3, wh, wl);
    k_scan1<<<NB, 256>>>(cnt, rowptr, blk, dis, N);
    k_scan2<<<1, 256>>>(blk, NB);
    k_scan3<<<NB, 256>>>(rowptr, cur, blk, N, E);
    k_fill <<<(E + 255) / 256, 256>>>(src, tgt, dis, cur, epack, E);

    // ---- layer 1 (gather also re-zeroes cnt for the next launch) ----
    k_gemm  <<<gemm_blocks, 256, GEMM_SMEM>>>(xh, xl, wh, wl, hw, N);
    k_gather<<<GATHER_BLOCKS, 256>>>(rowptr, epack, hw, b1, dis, xh, xl, 1, cnt, pool, N);

    // ---- layer 2 ----
    k_gemm  <<<gemm_blocks, 256, GEMM_SMEM>>>(xh, xl, wh + WSTRIDE, wl + WSTRIDE, hw, N);
    k_gather<<<GATHER_BLOCKS, 256>>>(rowptr, epack, hw, b2, dis, xh, xl, 1, (int*)0, pool + HDIM, N);

    // ---- layer 3 ----
    k_gemm  <<<gemm_blocks, 256, GEMM_SMEM>>>(xh, xl, wh + 2 * WSTRIDE, wl + 2 * WSTRIDE, hw, N);
    k_gather<<<GATHER_BLOCKS, 256>>>(rowptr, epack, hw, b3, dis, xh, xl, 0, (int*)0, pool + 2 * HDIM, N);

    k_mlp<<<1, 128>>>(pool, fw1, fb1, fw2, fb2, fw3, fb3, (float*)d_out);
}